// round 2
// baseline (speedup 1.0000x reference)
#include <cuda_runtime.h>
#include <cuda_bf16.h>
#include <math.h>

#define N_NODES 10000
#define N_EDGES 200000
#define NF 128

// ---- output offsets (pytree leaf order) ----
#define OFF_X     0
#define OFF_LOSS  40000
#define OFF_BETA  40001
#define OFF_RES   40002
#define OFF_X1    240002
#define OFF_X2    1520002
#define OFF_X3    2800002
#define OFF_X4    4080002
#define OFF_E1    5360002
#define OFF_E2    30960002
#define OFF_E3    56560002
#define OFF_E4    82160002

// ---- scratch (no allocations allowed) ----
__device__ float g_eam[N_EDGES * 4];
__device__ float g_xsum[N_NODES * NF];
__device__ int   g_cnt[N_NODES];
__device__ float g_loss[1];

// ---------------- utility kernels ----------------
__global__ void zero_f(float* p, int n) {
    int i = blockIdx.x * blockDim.x + threadIdx.x;
    if (i < n) p[i] = 0.f;
}
__global__ void zero_i(int* p, int n) {
    int i = blockIdx.x * blockDim.x + threadIdx.x;
    if (i < n) p[i] = 0;
}

__device__ __forceinline__ void qmul4(float qw,float qx,float qy,float qz,
                                      float rw,float rx,float ry,float rz,
                                      float& ow,float& ox,float& oy,float& oz) {
    ow = qw*rw - qx*rx - qy*ry - qz*rz;
    ox = qw*rx + qx*rw + qy*rz - qz*ry;
    oy = qw*ry - qx*rz + qy*rw + qz*rx;
    oz = qw*rz + qx*ry - qy*rx + qz*rw;
}

// eam = qmul(qmul(inv(x_org[col]), edge_attr), x_org[row]); also count rows
__global__ void prep_kernel(const float* __restrict__ x_org,
                            const float* __restrict__ edge_attr,
                            const int* __restrict__ row,
                            const int* __restrict__ col,
                            float* __restrict__ eam,
                            int* __restrict__ cnt) {
    int e = blockIdx.x * blockDim.x + threadIdx.x;
    if (e >= N_EDGES) return;
    int r = row[e], c = col[e];
    float cw = x_org[c*4+0], cx = -x_org[c*4+1], cy = -x_org[c*4+2], cz = -x_org[c*4+3];
    float aw = edge_attr[e*4+0], ax = edge_attr[e*4+1], ay = edge_attr[e*4+2], az = edge_attr[e*4+3];
    float tw,tx,ty,tz;
    qmul4(cw,cx,cy,cz, aw,ax,ay,az, tw,tx,ty,tz);
    float rw = x_org[r*4+0], rx = x_org[r*4+1], ry = x_org[r*4+2], rz = x_org[r*4+3];
    float ow,ox,oy,oz;
    qmul4(tw,tx,ty,tz, rw,rx,ry,rz, ow,ox,oy,oz);
    eam[e*4+0]=ow; eam[e*4+1]=ox; eam[e*4+2]=oy; eam[e*4+3]=oz;
    atomicAdd(&cnt[r], 1);
}

// ---------------- fused gather + GEMM ----------------
struct GemmParams {
    const float* base[6];
    int end[6];      // cumulative end in K
    int mode[6];     // 0=index by row, 1=by col, 2=by edge
    int nsegs;
    int K;
    const float* W;  // K x 128 row-major
    const float* b;  // 128
    float* e_out;    // E x 128 (relu(m))
    float* xsum;     // N x 128 (sum of m)
    const int* row;
    const int* col;
};

#define BM 64
#define BK 32

__global__ void __launch_bounds__(256)
edge_gemm_kernel(GemmParams p) {
    __shared__ float As[BM][BK + 1];
    __shared__ float Bs[BK][128];

    int tid = threadIdx.x;
    int e_base = blockIdx.x * BM;
    int lane = tid & 31, wrp = tid >> 5;

    // edges loaded by this warp in A-tile: wrp*8 .. wrp*8+7
    int lrow[8], lcol[8];
#pragma unroll
    for (int i = 0; i < 8; i++) {
        int e = e_base + wrp * 8 + i;
        lrow[i] = p.row[e];
        lcol[i] = p.col[e];
    }

    int tx = tid & 15;       // 16 groups of 8 cols
    int ty = tid >> 4;       // 16 groups of 4 edges
    float acc[4][8];
#pragma unroll
    for (int i = 0; i < 4; i++)
#pragma unroll
        for (int j = 0; j < 8; j++) acc[i][j] = 0.f;

    int nChunks = (p.K + BK - 1) / BK;
    for (int ch = 0; ch < nChunks; ch++) {
        int k0 = ch * BK;
        // ---- A tile load: lane = k, warp covers 8 edges ----
        int k = k0 + lane;
        const float* bp = nullptr; int mode = 2, width = 0, loc = 0;
        if (k < p.K) {
            int start = 0;
            for (int s = 0; s < p.nsegs; s++) {
                if (k < p.end[s]) { bp = p.base[s]; mode = p.mode[s]; width = p.end[s]-start; loc = k-start; break; }
                start = p.end[s];
            }
        }
#pragma unroll
        for (int i = 0; i < 8; i++) {
            float v = 0.f;
            if (bp) {
                int idx = (mode == 0) ? lrow[i] : ((mode == 1) ? lcol[i] : (e_base + wrp*8 + i));
                v = bp[(size_t)idx * width + loc];
            }
            As[wrp*8 + i][lane] = v;
        }
        // ---- B tile load (float4, coalesced) ----
#pragma unroll
        for (int i = 0; i < 4; i++) {
            int idx = tid + i * 256;        // 0..1023 float4's
            int kb = idx >> 5;              // 32 float4 per 128-float row
            int n4 = idx & 31;
            float4 v = make_float4(0.f,0.f,0.f,0.f);
            if (k0 + kb < p.K)
                v = reinterpret_cast<const float4*>(p.W + (size_t)(k0 + kb) * 128)[n4];
            reinterpret_cast<float4*>(&Bs[kb][0])[n4] = v;
        }
        __syncthreads();
        // ---- compute ----
#pragma unroll
        for (int kk = 0; kk < BK; kk++) {
            float a0 = As[ty*4+0][kk];
            float a1 = As[ty*4+1][kk];
            float a2 = As[ty*4+2][kk];
            float a3 = As[ty*4+3][kk];
            float4 b0 = *reinterpret_cast<const float4*>(&Bs[kk][tx*8]);
            float4 b1 = *reinterpret_cast<const float4*>(&Bs[kk][tx*8+4]);
            float bb[8] = {b0.x,b0.y,b0.z,b0.w,b1.x,b1.y,b1.z,b1.w};
#pragma unroll
            for (int j = 0; j < 8; j++) {
                acc[0][j] = fmaf(a0, bb[j], acc[0][j]);
                acc[1][j] = fmaf(a1, bb[j], acc[1][j]);
                acc[2][j] = fmaf(a2, bb[j], acc[2][j]);
                acc[3][j] = fmaf(a3, bb[j], acc[3][j]);
            }
        }
        __syncthreads();
    }

    // ---- epilogue: bias, relu->e_out, atomic sum to xsum ----
    float bias[8];
#pragma unroll
    for (int j = 0; j < 8; j++) bias[j] = p.b[tx*8 + j];
#pragma unroll
    for (int i = 0; i < 4; i++) {
        int e = e_base + ty*4 + i;
        int rnode = p.row[e];
#pragma unroll
        for (int j = 0; j < 8; j++) {
            float m = acc[i][j] + bias[j];
            p.e_out[(size_t)e * 128 + tx*8 + j] = fmaxf(m, 0.f);
            atomicAdd(&p.xsum[rnode * 128 + tx*8 + j], m);
        }
    }
}

// x_next = relu(xsum / max(cnt,1))
__global__ void node_update(const float* __restrict__ xsum,
                            const int* __restrict__ cnt,
                            float* __restrict__ xout, int n_elems) {
    int i = blockIdx.x * blockDim.x + threadIdx.x;
    if (i >= n_elems) return;
    int node = i >> 7;
    float c = (float)max(cnt[node], 1);
    xout[i] = fmaxf(xsum[i] / c, 0.f);
}

// x = normalize(qmul(x4 @ lin1_w + lin1_b, x_org))
__global__ void lin1_kernel(const float* __restrict__ x4,
                            const float* __restrict__ w,
                            const float* __restrict__ bb,
                            const float* __restrict__ x_org,
                            float* __restrict__ xout) {
    int n = blockIdx.x * blockDim.x + threadIdx.x;
    if (n >= N_NODES) return;
    float q0 = bb[0], q1 = bb[1], q2 = bb[2], q3 = bb[3];
    for (int k = 0; k < 128; k++) {
        float v = x4[(size_t)n * 128 + k];
        q0 = fmaf(v, w[k*4+0], q0);
        q1 = fmaf(v, w[k*4+1], q1);
        q2 = fmaf(v, w[k*4+2], q2);
        q3 = fmaf(v, w[k*4+3], q3);
    }
    float rw = x_org[n*4+0], rx = x_org[n*4+1], ry = x_org[n*4+2], rz = x_org[n*4+3];
    float ow,ox,oy,oz;
    qmul4(q0,q1,q2,q3, rw,rx,ry,rz, ow,ox,oy,oz);
    float nn = sqrtf(ow*ow + ox*ox + oy*oy + oz*oz);
    nn = fmaxf(nn, 1e-12f);
    xout[n*4+0] = ow/nn; xout[n*4+1] = ox/nn; xout[n*4+2] = oy/nn; xout[n*4+3] = oz/nn;
}

__global__ void loss_kernel(const float* __restrict__ gt,
                            const float* __restrict__ x,
                            const int* __restrict__ row,
                            const int* __restrict__ col,
                            const float* __restrict__ beta_p,
                            float* __restrict__ loss_acc) {
    int e = blockIdx.x * blockDim.x + threadIdx.x;
    float local = 0.f;
    if (e < N_EDGES) {
        int r = row[e], c = col[e];
        // rel_gt = qmul(gt[c], inv(gt[r]))
        float aw = gt[c*4+0], ax = gt[c*4+1], ay = gt[c*4+2], az = gt[c*4+3];
        float bw = gt[r*4+0], bx = -gt[r*4+1], by = -gt[r*4+2], bz = -gt[r*4+3];
        float gw,gx,gy,gz;
        qmul4(aw,ax,ay,az, bw,bx,by,bz, gw,gx,gy,gz);
        // rel_x = qmul(x[c], inv(x[r]))
        float cw2 = x[c*4+0], cx2 = x[c*4+1], cy2 = x[c*4+2], cz2 = x[c*4+3];
        float dw = x[r*4+0], dx = -x[r*4+1], dy = -x[r*4+2], dz = -x[r*4+3];
        float xw,xx,xy,xz;
        qmul4(cw2,cx2,cy2,cz2, dw,dx,dy,dz, xw,xx,xy,xz);
        // l1 = normalize(qmul(inv(rel_gt), rel_x))
        float lw,lx,ly,lz;
        qmul4(gw,-gx,-gy,-gz, xw,xx,xy,xz, lw,lx,ly,lz);
        float nn = sqrtf(lw*lw + lx*lx + ly*ly + lz*lz);
        nn = fmaxf(nn, 1e-12f);
        lw /= nn; lx /= nn; ly /= nn; lz /= nn;
        float beta = beta_p[0];
        float d[4] = {fabsf(lw - 1.f), fabsf(lx), fabsf(ly), fabsf(lz)};
#pragma unroll
        for (int i = 0; i < 4; i++) {
            float v = d[i];
            local += (v < beta) ? (0.5f * v * v / beta) : (v - 0.5f * beta);
        }
    }
    __shared__ float sm[256];
    sm[threadIdx.x] = local;
    __syncthreads();
    for (int s = 128; s > 0; s >>= 1) {
        if (threadIdx.x < s) sm[threadIdx.x] += sm[threadIdx.x + s];
        __syncthreads();
    }
    if (threadIdx.x == 0) atomicAdd(loss_acc, sm[0]);
}

__global__ void finalize_kernel(const float* __restrict__ loss_acc,
                                const float* __restrict__ beta_p,
                                float* __restrict__ out) {
    out[OFF_LOSS] = loss_acc[0] / (float)(N_EDGES * 4);
    out[OFF_BETA] = beta_p[0];
}

// out_res = e4 @ lin2_w + lin2_b  (warp per edge)
__global__ void outres_kernel(const float* __restrict__ e4,
                              const float* __restrict__ w,
                              const float* __restrict__ b,
                              float* __restrict__ out) {
    int gw = (blockIdx.x * blockDim.x + threadIdx.x) >> 5;
    int lane = threadIdx.x & 31;
    if (gw >= N_EDGES) return;
    float s = 0.f;
#pragma unroll
    for (int k = lane; k < 128; k += 32)
        s = fmaf(e4[(size_t)gw * 128 + k], w[k], s);
#pragma unroll
    for (int o = 16; o > 0; o >>= 1) s += __shfl_down_sync(0xFFFFFFFFu, s, o);
    if (lane == 0) out[OFF_RES + gw] = s + b[0];
}

// ---------------- host ----------------
extern "C" void kernel_launch(void* const* d_in, const int* in_sizes, int n_in,
                              void* d_out, int out_size) {
    const float* x_org     = (const float*)d_in[0];
    const float* edge_attr = (const float*)d_in[1];
    const float* gt_q      = (const float*)d_in[2];
    const float* beta      = (const float*)d_in[3];
    const float* node_feat = (const float*)d_in[4];
    const float* edge_feat = (const float*)d_in[5];
    const float* W1 = (const float*)d_in[6];
    const float* b1 = (const float*)d_in[7];
    const float* W2 = (const float*)d_in[8];
    const float* b2 = (const float*)d_in[9];
    const float* W3 = (const float*)d_in[10];
    const float* b3 = (const float*)d_in[11];
    const float* W4 = (const float*)d_in[12];
    const float* b4 = (const float*)d_in[13];
    const float* lin1_w = (const float*)d_in[14];
    const float* lin1_b = (const float*)d_in[15];
    const float* lin2_w = (const float*)d_in[16];
    const float* lin2_b = (const float*)d_in[17];
    const int* ei = (const int*)d_in[18];
    const int* row = ei;
    const int* col = ei + N_EDGES;

    float* out = (float*)d_out;
    float* x1 = out + OFF_X1;
    float* x2 = out + OFF_X2;
    float* x3 = out + OFF_X3;
    float* x4 = out + OFF_X4;
    float* e1 = out + OFF_E1;
    float* e2 = out + OFF_E2;
    float* e3 = out + OFF_E3;
    float* e4 = out + OFF_E4;

    float *eam, *xsum, *lossacc;
    int* cnt;
    cudaGetSymbolAddress((void**)&eam, g_eam);
    cudaGetSymbolAddress((void**)&xsum, g_xsum);
    cudaGetSymbolAddress((void**)&lossacc, g_loss);
    cudaGetSymbolAddress((void**)&cnt, g_cnt);

    zero_i<<<(N_NODES + 255)/256, 256>>>(cnt, N_NODES);
    zero_f<<<1, 32>>>(lossacc, 1);
    prep_kernel<<<(N_EDGES + 255)/256, 256>>>(x_org, edge_attr, row, col, eam, cnt);

    auto run_layer = [&](GemmParams& p, float* xout) {
        zero_f<<<(N_NODES*128 + 255)/256, 256>>>(xsum, N_NODES*128);
        edge_gemm_kernel<<<N_EDGES / BM, 256>>>(p);
        node_update<<<(N_NODES*128 + 255)/256, 256>>>(xsum, cnt, xout, N_NODES*128);
    };

    // Layer 1: [node_feat[row],x_org[row] | node_feat[col],x_org[col] | edge_feat,eam]
    {
        GemmParams p;
        p.base[0]=node_feat; p.mode[0]=0; p.end[0]=128;
        p.base[1]=x_org;     p.mode[1]=0; p.end[1]=132;
        p.base[2]=node_feat; p.mode[2]=1; p.end[2]=260;
        p.base[3]=x_org;     p.mode[3]=1; p.end[3]=264;
        p.base[4]=edge_feat; p.mode[4]=2; p.end[4]=392;
        p.base[5]=eam;       p.mode[5]=2; p.end[5]=396;
        p.nsegs=6; p.K=396; p.W=W1; p.b=b1; p.e_out=e1; p.xsum=xsum; p.row=row; p.col=col;
        run_layer(p, x1);
    }
    // Layer 2: [x1[row] | x1[col] | eam, e1]
    {
        GemmParams p;
        p.base[0]=x1;  p.mode[0]=0; p.end[0]=128;
        p.base[1]=x1;  p.mode[1]=1; p.end[1]=256;
        p.base[2]=eam; p.mode[2]=2; p.end[2]=260;
        p.base[3]=e1;  p.mode[3]=2; p.end[3]=388;
        p.nsegs=4; p.K=388; p.W=W2; p.b=b2; p.e_out=e2; p.xsum=xsum; p.row=row; p.col=col;
        run_layer(p, x2);
    }
    // Layer 3: [x2[row],x1[row] | x2[col],x1[col] | e2,e1]
    {
        GemmParams p;
        p.base[0]=x2; p.mode[0]=0; p.end[0]=128;
        p.base[1]=x1; p.mode[1]=0; p.end[1]=256;
        p.base[2]=x2; p.mode[2]=1; p.end[2]=384;
        p.base[3]=x1; p.mode[3]=1; p.end[3]=512;
        p.base[4]=e2; p.mode[4]=2; p.end[4]=640;
        p.base[5]=e1; p.mode[5]=2; p.end[5]=768;
        p.nsegs=6; p.K=768; p.W=W3; p.b=b3; p.e_out=e3; p.xsum=xsum; p.row=row; p.col=col;
        run_layer(p, x3);
    }
    // Layer 4: [x3[row],x2[row] | x3[col],x2[col] | e3,e2]
    {
        GemmParams p;
        p.base[0]=x3; p.mode[0]=0; p.end[0]=128;
        p.base[1]=x2; p.mode[1]=0; p.end[1]=256;
        p.base[2]=x3; p.mode[2]=1; p.end[2]=384;
        p.base[3]=x2; p.mode[3]=1; p.end[3]=512;
        p.base[4]=e3; p.mode[4]=2; p.end[4]=640;
        p.base[5]=e2; p.mode[5]=2; p.end[5]=768;
        p.nsegs=6; p.K=768; p.W=W4; p.b=b4; p.e_out=e4; p.xsum=xsum; p.row=row; p.col=col;
        run_layer(p, x4);
    }

    lin1_kernel<<<(N_NODES + 255)/256, 256>>>(x4, lin1_w, lin1_b, x_org, out + OFF_X);
    loss_kernel<<<(N_EDGES + 255)/256, 256>>>(gt_q, out + OFF_X, row, col, beta, lossacc);
    finalize_kernel<<<1, 1>>>(lossacc, beta, out);
    outres_kernel<<<(N_EDGES*32 + 255)/256, 256>>>(e4, lin2_w, lin2_b, out);

    (void)in_sizes; (void)n_in; (void)out_size;
}

// round 3
// speedup vs baseline: 2.0575x; 2.0575x over previous
#include <cuda_runtime.h>
#include <cuda_bf16.h>
#include <math.h>

#define N_NODES 10000
#define N_EDGES 200000
#define NF 128

// ---- output offsets (pytree leaf order) ----
#define OFF_X     0
#define OFF_LOSS  40000
#define OFF_BETA  40001
#define OFF_RES   40002
#define OFF_X1    240002
#define OFF_X2    1520002
#define OFF_X3    2800002
#define OFF_X4    4080002
#define OFF_E1    5360002
#define OFF_E2    30960002
#define OFF_E3    56560002
#define OFF_E4    82160002

// ---- scratch (no allocations allowed) ----
__device__ float g_eam[N_EDGES * 4];
__device__ float g_xsum[N_NODES * NF];   // zero-initialized at load; invariant: zero after each launch
__device__ int   g_cnt[N_NODES];
__device__ float g_loss[1];

// ---------------- utility kernels ----------------
__global__ void zero_f(float* p, int n) {
    int i = blockIdx.x * blockDim.x + threadIdx.x;
    if (i < n) p[i] = 0.f;
}
__global__ void zero_i(int* p, int n) {
    int i = blockIdx.x * blockDim.x + threadIdx.x;
    if (i < n) p[i] = 0;
}

__device__ __forceinline__ void qmul4(float qw,float qx,float qy,float qz,
                                      float rw,float rx,float ry,float rz,
                                      float& ow,float& ox,float& oy,float& oz) {
    ow = qw*rw - qx*rx - qy*ry - qz*rz;
    ox = qw*rx + qx*rw + qy*rz - qz*ry;
    oy = qw*ry - qx*rz + qy*rw + qz*rx;
    oz = qw*rz + qx*ry - qy*rx + qz*rw;
}

__device__ __forceinline__ unsigned f2tf32(float f) {
    unsigned u;
    asm("cvt.rna.tf32.f32 %0, %1;" : "=r"(u) : "f"(f));
    return u;
}

// eam = qmul(qmul(inv(x_org[col]), edge_attr), x_org[row]); also count rows
__global__ void prep_kernel(const float* __restrict__ x_org,
                            const float* __restrict__ edge_attr,
                            const int* __restrict__ row,
                            const int* __restrict__ col,
                            float* __restrict__ eam,
                            int* __restrict__ cnt) {
    int e = blockIdx.x * blockDim.x + threadIdx.x;
    if (e >= N_EDGES) return;
    int r = row[e], c = col[e];
    float cw = x_org[c*4+0], cx = -x_org[c*4+1], cy = -x_org[c*4+2], cz = -x_org[c*4+3];
    float aw = edge_attr[e*4+0], ax = edge_attr[e*4+1], ay = edge_attr[e*4+2], az = edge_attr[e*4+3];
    float tw,tx,ty,tz;
    qmul4(cw,cx,cy,cz, aw,ax,ay,az, tw,tx,ty,tz);
    float rw = x_org[r*4+0], rx = x_org[r*4+1], ry = x_org[r*4+2], rz = x_org[r*4+3];
    float ow,ox,oy,oz;
    qmul4(tw,tx,ty,tz, rw,rx,ry,rz, ow,ox,oy,oz);
    eam[e*4+0]=ow; eam[e*4+1]=ox; eam[e*4+2]=oy; eam[e*4+3]=oz;
    atomicAdd(&cnt[r], 1);
}

// ---------------- fused gather + tf32 tensor-core GEMM ----------------
struct GemmParams {
    const float* base[6];
    int end[6];      // cumulative end in K
    int mode[6];     // 0=index by row, 1=by col, 2=by edge
    int nsegs;
    int K;
    const float* W;  // K x 128 row-major
    const float* b;  // 128
    float* e_out;    // E x 128 (relu(m))
    float* xsum;     // N x 128 (sum of m)
    const int* row;
    const int* col;
};

#define BM 64
#define BK 32
#define A_STRIDE 36    // bank = (4m + k) % 32 -> bijective over warp for frag loads
#define B_STRIDE 136   // bank = (8k + n) % 32 -> bijective over warp for frag loads

__global__ void __launch_bounds__(256, 2)
edge_gemm_tc(GemmParams p) {
    __shared__ float As[BM][A_STRIDE];
    __shared__ float Bs[BK][B_STRIDE];

    int tid = threadIdx.x;
    int lane = tid & 31, wrp = tid >> 5;
    int e_base = blockIdx.x * BM;

    // ---- gather role: warp wrp loads edges wrp*8..wrp*8+7, lane = k within chunk
    int lrow[8], lcol[8];
#pragma unroll
    for (int i = 0; i < 8; i++) {
        int e = e_base + wrp * 8 + i;
        lrow[i] = p.row[e];
        lcol[i] = p.col[e];
    }

    // ---- compute role: warp (wm, wn) computes rows [wm*16,+16), cols [wn*64,+64)
    int wm = wrp & 3, wn = wrp >> 2;
    int m0 = wm * 16, nb = wn * 64;
    int g = lane >> 2, tg = lane & 3;

    float acc[8][4];
#pragma unroll
    for (int j = 0; j < 8; j++)
#pragma unroll
        for (int c = 0; c < 4; c++) acc[j][c] = 0.f;

    int nChunks = (p.K + BK - 1) / BK;
    for (int ch = 0; ch < nChunks; ch++) {
        int k0 = ch * BK;

        // ---- A tile gather (tf32-rounded) ----
        int k = k0 + lane;
        const float* bp = nullptr; int mode = 2, width = 0, loc = 0;
        if (k < p.K) {
            int start = 0;
            for (int s = 0; s < p.nsegs; s++) {
                if (k < p.end[s]) { bp = p.base[s]; mode = p.mode[s]; width = p.end[s]-start; loc = k-start; break; }
                start = p.end[s];
            }
        }
#pragma unroll
        for (int i = 0; i < 8; i++) {
            float v = 0.f;
            if (bp) {
                int idx = (mode == 0) ? lrow[i] : ((mode == 1) ? lcol[i] : (e_base + wrp*8 + i));
                v = bp[(size_t)idx * width + loc];
            }
            As[wrp*8 + i][lane] = __uint_as_float(f2tf32(v));
        }
        // ---- B tile load (tf32-rounded) ----
#pragma unroll
        for (int i = 0; i < 4; i++) {
            int idx = tid + i * 256;
            int kb = idx >> 5;
            int n4 = idx & 31;
            float4 v = make_float4(0.f,0.f,0.f,0.f);
            if (k0 + kb < p.K)
                v = reinterpret_cast<const float4*>(p.W + (size_t)(k0 + kb) * 128)[n4];
            v.x = __uint_as_float(f2tf32(v.x));
            v.y = __uint_as_float(f2tf32(v.y));
            v.z = __uint_as_float(f2tf32(v.z));
            v.w = __uint_as_float(f2tf32(v.w));
            *reinterpret_cast<float4*>(&Bs[kb][n4*4]) = v;
        }
        __syncthreads();

        // ---- tensor-core compute: 4 k-steps of 8 ----
#pragma unroll
        for (int ks = 0; ks < 4; ks++) {
            int kk = ks * 8;
            unsigned a0 = __float_as_uint(As[m0 + g    ][kk + tg    ]);
            unsigned a1 = __float_as_uint(As[m0 + g + 8][kk + tg    ]);
            unsigned a2 = __float_as_uint(As[m0 + g    ][kk + tg + 4]);
            unsigned a3 = __float_as_uint(As[m0 + g + 8][kk + tg + 4]);
#pragma unroll
            for (int j = 0; j < 8; j++) {
                unsigned b0 = __float_as_uint(Bs[kk + tg    ][nb + j*8 + g]);
                unsigned b1 = __float_as_uint(Bs[kk + tg + 4][nb + j*8 + g]);
                asm volatile(
                    "mma.sync.aligned.m16n8k8.row.col.f32.tf32.tf32.f32 "
                    "{%0,%1,%2,%3}, {%4,%5,%6,%7}, {%8,%9}, {%0,%1,%2,%3};"
                    : "+f"(acc[j][0]), "+f"(acc[j][1]), "+f"(acc[j][2]), "+f"(acc[j][3])
                    : "r"(a0), "r"(a1), "r"(a2), "r"(a3), "r"(b0), "r"(b1));
            }
        }
        __syncthreads();
    }

    // ---- epilogue: bias, relu->e_out, atomic sum to xsum ----
    int eA = e_base + m0 + g;
    int eB = eA + 8;
    int rA = p.row[eA], rB = p.row[eB];
#pragma unroll
    for (int j = 0; j < 8; j++) {
        int n = nb + j*8 + tg*2;
        float b0 = p.b[n], b1 = p.b[n+1];
        float mA0 = acc[j][0] + b0, mA1 = acc[j][1] + b1;
        float mB0 = acc[j][2] + b0, mB1 = acc[j][3] + b1;
        float2 oA = make_float2(fmaxf(mA0, 0.f), fmaxf(mA1, 0.f));
        float2 oB = make_float2(fmaxf(mB0, 0.f), fmaxf(mB1, 0.f));
        *reinterpret_cast<float2*>(&p.e_out[(size_t)eA * 128 + n]) = oA;
        *reinterpret_cast<float2*>(&p.e_out[(size_t)eB * 128 + n]) = oB;
        atomicAdd(&p.xsum[rA * 128 + n    ], mA0);
        atomicAdd(&p.xsum[rA * 128 + n + 1], mA1);
        atomicAdd(&p.xsum[rB * 128 + n    ], mB0);
        atomicAdd(&p.xsum[rB * 128 + n + 1], mB1);
    }
}

// x_next = relu(xsum / max(cnt,1)); also resets xsum to 0 for the next layer
__global__ void node_update(float* __restrict__ xsum,
                            const int* __restrict__ cnt,
                            float* __restrict__ xout, int n_elems) {
    int i = blockIdx.x * blockDim.x + threadIdx.x;
    if (i >= n_elems) return;
    int node = i >> 7;
    float c = (float)max(cnt[node], 1);
    float v = xsum[i];
    xsum[i] = 0.f;
    xout[i] = fmaxf(v / c, 0.f);
}

// x = normalize(qmul(x4 @ lin1_w + lin1_b, x_org))
__global__ void lin1_kernel(const float* __restrict__ x4,
                            const float* __restrict__ w,
                            const float* __restrict__ bb,
                            const float* __restrict__ x_org,
                            float* __restrict__ xout) {
    int n = blockIdx.x * blockDim.x + threadIdx.x;
    if (n >= N_NODES) return;
    float q0 = bb[0], q1 = bb[1], q2 = bb[2], q3 = bb[3];
    for (int k = 0; k < 128; k++) {
        float v = x4[(size_t)n * 128 + k];
        q0 = fmaf(v, w[k*4+0], q0);
        q1 = fmaf(v, w[k*4+1], q1);
        q2 = fmaf(v, w[k*4+2], q2);
        q3 = fmaf(v, w[k*4+3], q3);
    }
    float rw = x_org[n*4+0], rx = x_org[n*4+1], ry = x_org[n*4+2], rz = x_org[n*4+3];
    float ow,ox,oy,oz;
    qmul4(q0,q1,q2,q3, rw,rx,ry,rz, ow,ox,oy,oz);
    float nn = sqrtf(ow*ow + ox*ox + oy*oy + oz*oz);
    nn = fmaxf(nn, 1e-12f);
    xout[n*4+0] = ow/nn; xout[n*4+1] = ox/nn; xout[n*4+2] = oy/nn; xout[n*4+3] = oz/nn;
}

__global__ void loss_kernel(const float* __restrict__ gt,
                            const float* __restrict__ x,
                            const int* __restrict__ row,
                            const int* __restrict__ col,
                            const float* __restrict__ beta_p,
                            float* __restrict__ loss_acc) {
    int e = blockIdx.x * blockDim.x + threadIdx.x;
    float local = 0.f;
    if (e < N_EDGES) {
        int r = row[e], c = col[e];
        float aw = gt[c*4+0], ax = gt[c*4+1], ay = gt[c*4+2], az = gt[c*4+3];
        float bw = gt[r*4+0], bx = -gt[r*4+1], by = -gt[r*4+2], bz = -gt[r*4+3];
        float gw,gx,gy,gz;
        qmul4(aw,ax,ay,az, bw,bx,by,bz, gw,gx,gy,gz);
        float cw2 = x[c*4+0], cx2 = x[c*4+1], cy2 = x[c*4+2], cz2 = x[c*4+3];
        float dw = x[r*4+0], dx = -x[r*4+1], dy = -x[r*4+2], dz = -x[r*4+3];
        float xw,xx,xy,xz;
        qmul4(cw2,cx2,cy2,cz2, dw,dx,dy,dz, xw,xx,xy,xz);
        float lw,lx,ly,lz;
        qmul4(gw,-gx,-gy,-gz, xw,xx,xy,xz, lw,lx,ly,lz);
        float nn = sqrtf(lw*lw + lx*lx + ly*ly + lz*lz);
        nn = fmaxf(nn, 1e-12f);
        lw /= nn; lx /= nn; ly /= nn; lz /= nn;
        float beta = beta_p[0];
        float d[4] = {fabsf(lw - 1.f), fabsf(lx), fabsf(ly), fabsf(lz)};
#pragma unroll
        for (int i = 0; i < 4; i++) {
            float v = d[i];
            local += (v < beta) ? (0.5f * v * v / beta) : (v - 0.5f * beta);
        }
    }
    __shared__ float sm[256];
    sm[threadIdx.x] = local;
    __syncthreads();
    for (int s = 128; s > 0; s >>= 1) {
        if (threadIdx.x < s) sm[threadIdx.x] += sm[threadIdx.x + s];
        __syncthreads();
    }
    if (threadIdx.x == 0) atomicAdd(loss_acc, sm[0]);
}

__global__ void finalize_kernel(const float* __restrict__ loss_acc,
                                const float* __restrict__ beta_p,
                                float* __restrict__ out) {
    out[OFF_LOSS] = loss_acc[0] / (float)(N_EDGES * 4);
    out[OFF_BETA] = beta_p[0];
}

// out_res = e4 @ lin2_w + lin2_b  (warp per edge)
__global__ void outres_kernel(const float* __restrict__ e4,
                              const float* __restrict__ w,
                              const float* __restrict__ b,
                              float* __restrict__ out) {
    int gw = (blockIdx.x * blockDim.x + threadIdx.x) >> 5;
    int lane = threadIdx.x & 31;
    if (gw >= N_EDGES) return;
    float s = 0.f;
#pragma unroll
    for (int k = lane; k < 128; k += 32)
        s = fmaf(e4[(size_t)gw * 128 + k], w[k], s);
#pragma unroll
    for (int o = 16; o > 0; o >>= 1) s += __shfl_down_sync(0xFFFFFFFFu, s, o);
    if (lane == 0) out[OFF_RES + gw] = s + b[0];
}

// ---------------- host ----------------
extern "C" void kernel_launch(void* const* d_in, const int* in_sizes, int n_in,
                              void* d_out, int out_size) {
    const float* x_org     = (const float*)d_in[0];
    const float* edge_attr = (const float*)d_in[1];
    const float* gt_q      = (const float*)d_in[2];
    const float* beta      = (const float*)d_in[3];
    const float* node_feat = (const float*)d_in[4];
    const float* edge_feat = (const float*)d_in[5];
    const float* W1 = (const float*)d_in[6];
    const float* b1 = (const float*)d_in[7];
    const float* W2 = (const float*)d_in[8];
    const float* b2 = (const float*)d_in[9];
    const float* W3 = (const float*)d_in[10];
    const float* b3 = (const float*)d_in[11];
    const float* W4 = (const float*)d_in[12];
    const float* b4 = (const float*)d_in[13];
    const float* lin1_w = (const float*)d_in[14];
    const float* lin1_b = (const float*)d_in[15];
    const float* lin2_w = (const float*)d_in[16];
    const float* lin2_b = (const float*)d_in[17];
    const int* ei = (const int*)d_in[18];
    const int* row = ei;
    const int* col = ei + N_EDGES;

    float* out = (float*)d_out;
    float* x1 = out + OFF_X1;
    float* x2 = out + OFF_X2;
    float* x3 = out + OFF_X3;
    float* x4 = out + OFF_X4;
    float* e1 = out + OFF_E1;
    float* e2 = out + OFF_E2;
    float* e3 = out + OFF_E3;
    float* e4 = out + OFF_E4;

    float *eam, *xsum, *lossacc;
    int* cnt;
    cudaGetSymbolAddress((void**)&eam, g_eam);
    cudaGetSymbolAddress((void**)&xsum, g_xsum);
    cudaGetSymbolAddress((void**)&lossacc, g_loss);
    cudaGetSymbolAddress((void**)&cnt, g_cnt);

    zero_i<<<(N_NODES + 255)/256, 256>>>(cnt, N_NODES);
    zero_f<<<1, 32>>>(lossacc, 1);
    prep_kernel<<<(N_EDGES + 255)/256, 256>>>(x_org, edge_attr, row, col, eam, cnt);

    auto run_layer = [&](GemmParams& p, float* xout) {
        edge_gemm_tc<<<N_EDGES / BM, 256>>>(p);
        node_update<<<(N_NODES*128 + 255)/256, 256>>>(xsum, cnt, xout, N_NODES*128);
    };

    // Layer 1: [node_feat[row],x_org[row] | node_feat[col],x_org[col] | edge_feat,eam]
    {
        GemmParams p;
        p.base[0]=node_feat; p.mode[0]=0; p.end[0]=128;
        p.base[1]=x_org;     p.mode[1]=0; p.end[1]=132;
        p.base[2]=node_feat; p.mode[2]=1; p.end[2]=260;
        p.base[3]=x_org;     p.mode[3]=1; p.end[3]=264;
        p.base[4]=edge_feat; p.mode[4]=2; p.end[4]=392;
        p.base[5]=eam;       p.mode[5]=2; p.end[5]=396;
        p.nsegs=6; p.K=396; p.W=W1; p.b=b1; p.e_out=e1; p.xsum=xsum; p.row=row; p.col=col;
        run_layer(p, x1);
    }
    // Layer 2: [x1[row] | x1[col] | eam, e1]
    {
        GemmParams p;
        p.base[0]=x1;  p.mode[0]=0; p.end[0]=128;
        p.base[1]=x1;  p.mode[1]=1; p.end[1]=256;
        p.base[2]=eam; p.mode[2]=2; p.end[2]=260;
        p.base[3]=e1;  p.mode[3]=2; p.end[3]=388;
        p.nsegs=4; p.K=388; p.W=W2; p.b=b2; p.e_out=e2; p.xsum=xsum; p.row=row; p.col=col;
        run_layer(p, x2);
    }
    // Layer 3: [x2[row],x1[row] | x2[col],x1[col] | e2,e1]
    {
        GemmParams p;
        p.base[0]=x2; p.mode[0]=0; p.end[0]=128;
        p.base[1]=x1; p.mode[1]=0; p.end[1]=256;
        p.base[2]=x2; p.mode[2]=1; p.end[2]=384;
        p.base[3]=x1; p.mode[3]=1; p.end[3]=512;
        p.base[4]=e2; p.mode[4]=2; p.end[4]=640;
        p.base[5]=e1; p.mode[5]=2; p.end[5]=768;
        p.nsegs=6; p.K=768; p.W=W3; p.b=b3; p.e_out=e3; p.xsum=xsum; p.row=row; p.col=col;
        run_layer(p, x3);
    }
    // Layer 4: [x3[row],x2[row] | x3[col],x2[col] | e3,e2]
    {
        GemmParams p;
        p.base[0]=x3; p.mode[0]=0; p.end[0]=128;
        p.base[1]=x2; p.mode[1]=0; p.end[1]=256;
        p.base[2]=x3; p.mode[2]=1; p.end[2]=384;
        p.base[3]=x2; p.mode[3]=1; p.end[3]=512;
        p.base[4]=e3; p.mode[4]=2; p.end[4]=640;
        p.base[5]=e2; p.mode[5]=2; p.end[5]=768;
        p.nsegs=6; p.K=768; p.W=W4; p.b=b4; p.e_out=e4; p.xsum=xsum; p.row=row; p.col=col;
        run_layer(p, x4);
    }

    lin1_kernel<<<(N_NODES + 255)/256, 256>>>(x4, lin1_w, lin1_b, x_org, out + OFF_X);
    loss_kernel<<<(N_EDGES + 255)/256, 256>>>(gt_q, out + OFF_X, row, col, beta, lossacc);
    finalize_kernel<<<1, 1>>>(lossacc, beta, out);
    outres_kernel<<<(N_EDGES*32 + 255)/256, 256>>>(e4, lin2_w, lin2_b, out);

    (void)in_sizes; (void)n_in; (void)out_size;
}

// round 4
// speedup vs baseline: 4.4887x; 2.1817x over previous
#include <cuda_runtime.h>
#include <math.h>

#define N_NODES 10000
#define N_EDGES 200000

// ---- output offsets (pytree leaf order) ----
#define OFF_X     0
#define OFF_LOSS  40000
#define OFF_BETA  40001
#define OFF_RES   40002
#define OFF_X1    240002
#define OFF_X2    1520002
#define OFF_X3    2800002
#define OFF_X4    4080002
#define OFF_E1    5360002
#define OFF_E2    30960002
#define OFF_E3    56560002
#define OFF_E4    82160002

// ---- scratch (no allocations allowed) ----
__device__ float g_xsum[N_NODES * 128];   // zero-init at load; invariant: zero after each launch
__device__ int   g_cnt[N_NODES];
__device__ float g_loss[1];
// tf32-rounded operand copies (GEMM A/B inputs)
__device__ float g_nf_t[N_NODES * 128];
__device__ float g_xorg_t[N_NODES * 4];
__device__ float g_ef_t[N_EDGES * 128];
__device__ float g_eam_t[N_EDGES * 4];
__device__ float g_x1t[N_NODES * 128];
__device__ float g_x2t[N_NODES * 128];
__device__ float g_x3t[N_NODES * 128];
__device__ float g_e1t[N_EDGES * 128];
__device__ float g_e2t[N_EDGES * 128];
__device__ float g_e3t[N_EDGES * 128];
__device__ float g_Wt[2320 * 128];        // W1|W2|W3|W4 tf32

__device__ __forceinline__ unsigned f2tf32(float f) {
    unsigned u;
    asm("cvt.rna.tf32.f32 %0, %1;" : "=r"(u) : "f"(f));
    return u;
}
__device__ __forceinline__ float tf32f(float f) { return __uint_as_float(f2tf32(f)); }

__device__ __forceinline__ void qmul4(float qw,float qx,float qy,float qz,
                                      float rw,float rx,float ry,float rz,
                                      float& ow,float& ox,float& oy,float& oz) {
    ow = qw*rw - qx*rx - qy*ry - qz*rz;
    ox = qw*rx + qx*rw + qy*rz - qz*ry;
    oy = qw*ry - qx*rz + qy*rw + qz*rx;
    oz = qw*rz + qx*ry - qy*rx + qz*rw;
}

// ---------------- small kernels ----------------
__global__ void zero_f(float* p, int n) {
    int i = blockIdx.x * blockDim.x + threadIdx.x;
    if (i < n) p[i] = 0.f;
}
__global__ void zero_i(int* p, int n) {
    int i = blockIdx.x * blockDim.x + threadIdx.x;
    if (i < n) p[i] = 0;
}
__global__ void conv_tf32(const float* __restrict__ in, float* __restrict__ out, int n) {
    int i = blockIdx.x * blockDim.x + threadIdx.x;
    if (i < n) out[i] = tf32f(in[i]);
}

// eam = qmul(qmul(inv(x_org[col]), edge_attr), x_org[row]) -> tf32; count rows
__global__ void prep_kernel(const float* __restrict__ x_org,
                            const float* __restrict__ edge_attr,
                            const int* __restrict__ row,
                            const int* __restrict__ col,
                            float* __restrict__ eam_t,
                            int* __restrict__ cnt) {
    int e = blockIdx.x * blockDim.x + threadIdx.x;
    if (e >= N_EDGES) return;
    int r = row[e], c = col[e];
    float cw = x_org[c*4+0], cx = -x_org[c*4+1], cy = -x_org[c*4+2], cz = -x_org[c*4+3];
    float aw = edge_attr[e*4+0], ax = edge_attr[e*4+1], ay = edge_attr[e*4+2], az = edge_attr[e*4+3];
    float tw,tx,ty,tz;
    qmul4(cw,cx,cy,cz, aw,ax,ay,az, tw,tx,ty,tz);
    float rw = x_org[r*4+0], rx = x_org[r*4+1], ry = x_org[r*4+2], rz = x_org[r*4+3];
    float ow,ox,oy,oz;
    qmul4(tw,tx,ty,tz, rw,rx,ry,rz, ow,ox,oy,oz);
    eam_t[e*4+0]=tf32f(ow); eam_t[e*4+1]=tf32f(ox);
    eam_t[e*4+2]=tf32f(oy); eam_t[e*4+3]=tf32f(oz);
    atomicAdd(&cnt[r], 1);
}

// ---------------- fused gather + tf32 tensor GEMM (cp.async pipelined) ----------------
struct GemmParams {
    const float* base[6];  // tf32 buffers
    int end[6];
    int mode[6];           // 0=row, 1=col, 2=edge
    int nsegs;
    int K;
    const float* W;        // tf32, K x 128
    const float* b;        // fp32 bias
    float* e_out;          // fp32 relu(m)
    float* et;             // tf32 relu(m) or nullptr
    float* xsum;
    const int* row;
    const int* col;
};

#define BM 128
#define BK 16
#define A_ST 20     // bank=(20m+k)%32: {0,20,8,28,16,4,24,12}+tg -> bijective
#define B_ST 136    // bank=(8k+n)%32 bijective over fragment pattern

__device__ __forceinline__ void cpa4(unsigned dst, const float* src, int sz) {
    asm volatile("cp.async.ca.shared.global [%0], [%1], 4, %2;"
                 :: "r"(dst), "l"(src), "r"(sz));
}
__device__ __forceinline__ void cpa16(unsigned dst, const float* src, int sz) {
    asm volatile("cp.async.cg.shared.global [%0], [%1], 16, %2;"
                 :: "r"(dst), "l"(src), "r"(sz));
}
__device__ __forceinline__ void cp_commit() {
    asm volatile("cp.async.commit_group;");
}
template<int N> __device__ __forceinline__ void cp_wait() {
    asm volatile("cp.async.wait_group %0;" :: "n"(N));
}

__global__ void __launch_bounds__(256, 2)
edge_gemm_tc(GemmParams p) {
    __shared__ __align__(16) float As[2][BM][A_ST];
    __shared__ __align__(16) float Bs[2][BK][B_ST];

    int tid = threadIdx.x;
    int lane = tid & 31, wrp = tid >> 5;
    int e_base = blockIdx.x * BM;

    // gather role: thread covers rows rgrp*8..+8 at column kk_t of each chunk
    int kk_t = tid & 15, rgrp = tid >> 4;
    int er[8], ec[8];
#pragma unroll
    for (int i = 0; i < 8; i++) {
        int e = min(e_base + rgrp * 8 + i, N_EDGES - 1);
        er[i] = p.row[e];
        ec[i] = p.col[e];
    }

    // compute role: warp (wm,wn) does 32x64 at (wm*32, wn*64)
    int wm = wrp & 3, wn = wrp >> 2;
    int m0 = wm * 32, nb = wn * 64;
    int g = lane >> 2, tg = lane & 3;

    float acc[2][8][4];
#pragma unroll
    for (int mt = 0; mt < 2; mt++)
#pragma unroll
        for (int j = 0; j < 8; j++)
#pragma unroll
            for (int c = 0; c < 4; c++) acc[mt][j][c] = 0.f;

    int nCh = (p.K + BK - 1) / BK;

    auto load_tile = [&](int ch, int buf) {
        int k0 = ch * BK;
        // A gather
        int k = k0 + kk_t;
        const float* bp = p.base[0];
        int width = 1, loc = 0, mode = 2, sz = 0;
        if (k < p.K) {
            int start = 0;
#pragma unroll
            for (int s = 0; s < 6; s++) {
                if (s < p.nsegs && k < p.end[s]) {
                    bp = p.base[s]; mode = p.mode[s];
                    width = p.end[s] - start; loc = k - start; sz = 4;
                    break;
                }
                start = p.end[s];
            }
        }
#pragma unroll
        for (int i = 0; i < 8; i++) {
            int idx = (mode == 0) ? er[i] : ((mode == 1) ? ec[i]
                        : min(e_base + rgrp*8 + i, N_EDGES - 1));
            const float* src = bp + (size_t)idx * width + loc;
            unsigned dst = (unsigned)__cvta_generic_to_shared(&As[buf][rgrp*8 + i][kk_t]);
            cpa4(dst, src, sz);
        }
        // B tile: 16x128 via float4
#pragma unroll
        for (int t = 0; t < 2; t++) {
            int idx = tid + t * 256;
            int r = idx >> 5, c4 = idx & 31;
            int kr = k0 + r;
            int sz16 = (kr < p.K) ? 16 : 0;
            int krc = min(kr, p.K - 1);
            const float* src = p.W + (size_t)krc * 128 + c4 * 4;
            unsigned dst = (unsigned)__cvta_generic_to_shared(&Bs[buf][r][c4 * 4]);
            cpa16(dst, src, sz16);
        }
    };

    auto compute = [&](int buf) {
#pragma unroll
        for (int ks = 0; ks < 2; ks++) {
            int kk = ks * 8;
            unsigned a[2][4];
#pragma unroll
            for (int mt = 0; mt < 2; mt++) {
                int r = m0 + mt * 16;
                a[mt][0] = __float_as_uint(As[buf][r + g    ][kk + tg    ]);
                a[mt][1] = __float_as_uint(As[buf][r + g + 8][kk + tg    ]);
                a[mt][2] = __float_as_uint(As[buf][r + g    ][kk + tg + 4]);
                a[mt][3] = __float_as_uint(As[buf][r + g + 8][kk + tg + 4]);
            }
#pragma unroll
            for (int j = 0; j < 8; j++) {
                unsigned b0 = __float_as_uint(Bs[buf][kk + tg    ][nb + j*8 + g]);
                unsigned b1 = __float_as_uint(Bs[buf][kk + tg + 4][nb + j*8 + g]);
#pragma unroll
                for (int mt = 0; mt < 2; mt++) {
                    asm volatile(
                        "mma.sync.aligned.m16n8k8.row.col.f32.tf32.tf32.f32 "
                        "{%0,%1,%2,%3}, {%4,%5,%6,%7}, {%8,%9}, {%0,%1,%2,%3};"
                        : "+f"(acc[mt][j][0]), "+f"(acc[mt][j][1]),
                          "+f"(acc[mt][j][2]), "+f"(acc[mt][j][3])
                        : "r"(a[mt][0]), "r"(a[mt][1]), "r"(a[mt][2]), "r"(a[mt][3]),
                          "r"(b0), "r"(b1));
                }
            }
        }
    };

    // 2-stage pipeline
    load_tile(0, 0); cp_commit();
    if (nCh > 1) { load_tile(1, 1); cp_commit(); }
    for (int ch = 0; ch < nCh; ch++) {
        if (ch + 1 < nCh) cp_wait<1>(); else cp_wait<0>();
        __syncthreads();
        compute(ch & 1);
        __syncthreads();
        if (ch + 2 < nCh) { load_tile(ch + 2, ch & 1); cp_commit(); }
    }

    // ---- epilogue ----
#pragma unroll
    for (int mt = 0; mt < 2; mt++) {
        int eA = e_base + m0 + mt * 16 + g;
        int eB = eA + 8;
        bool vA = eA < N_EDGES, vB = eB < N_EDGES;
        int rA = vA ? p.row[eA] : 0;
        int rB = vB ? p.row[eB] : 0;
#pragma unroll
        for (int j = 0; j < 8; j++) {
            int n = nb + j*8 + tg*2;
            float b0 = p.b[n], b1 = p.b[n+1];
            float mA0 = acc[mt][j][0] + b0, mA1 = acc[mt][j][1] + b1;
            float mB0 = acc[mt][j][2] + b0, mB1 = acc[mt][j][3] + b1;
            if (vA) {
                float oa0 = fmaxf(mA0, 0.f), oa1 = fmaxf(mA1, 0.f);
                *reinterpret_cast<float2*>(&p.e_out[(size_t)eA*128 + n]) = make_float2(oa0, oa1);
                if (p.et)
                    *reinterpret_cast<float2*>(&p.et[(size_t)eA*128 + n]) =
                        make_float2(tf32f(oa0), tf32f(oa1));
                atomicAdd(&p.xsum[rA*128 + n    ], mA0);
                atomicAdd(&p.xsum[rA*128 + n + 1], mA1);
            }
            if (vB) {
                float ob0 = fmaxf(mB0, 0.f), ob1 = fmaxf(mB1, 0.f);
                *reinterpret_cast<float2*>(&p.e_out[(size_t)eB*128 + n]) = make_float2(ob0, ob1);
                if (p.et)
                    *reinterpret_cast<float2*>(&p.et[(size_t)eB*128 + n]) =
                        make_float2(tf32f(ob0), tf32f(ob1));
                atomicAdd(&p.xsum[rB*128 + n    ], mB0);
                atomicAdd(&p.xsum[rB*128 + n + 1], mB1);
            }
        }
    }
}

// x_next = relu(xsum / max(cnt,1)); resets xsum; optional tf32 copy
__global__ void node_update(float* __restrict__ xsum,
                            const int* __restrict__ cnt,
                            float* __restrict__ xout,
                            float* __restrict__ xt, int n_elems) {
    int i = blockIdx.x * blockDim.x + threadIdx.x;
    if (i >= n_elems) return;
    int node = i >> 7;
    float c = (float)max(cnt[node], 1);
    float v = xsum[i];
    xsum[i] = 0.f;
    float x = fmaxf(v / c, 0.f);
    xout[i] = x;
    if (xt) xt[i] = tf32f(x);
}

__global__ void lin1_kernel(const float* __restrict__ x4,
                            const float* __restrict__ w,
                            const float* __restrict__ bb,
                            const float* __restrict__ x_org,
                            float* __restrict__ xout) {
    int n = blockIdx.x * blockDim.x + threadIdx.x;
    if (n >= N_NODES) return;
    float q0 = bb[0], q1 = bb[1], q2 = bb[2], q3 = bb[3];
    for (int k = 0; k < 128; k++) {
        float v = x4[(size_t)n * 128 + k];
        q0 = fmaf(v, w[k*4+0], q0);
        q1 = fmaf(v, w[k*4+1], q1);
        q2 = fmaf(v, w[k*4+2], q2);
        q3 = fmaf(v, w[k*4+3], q3);
    }
    float rw = x_org[n*4+0], rx = x_org[n*4+1], ry = x_org[n*4+2], rz = x_org[n*4+3];
    float ow,ox,oy,oz;
    qmul4(q0,q1,q2,q3, rw,rx,ry,rz, ow,ox,oy,oz);
    float nn = sqrtf(ow*ow + ox*ox + oy*oy + oz*oz);
    nn = fmaxf(nn, 1e-12f);
    xout[n*4+0] = ow/nn; xout[n*4+1] = ox/nn; xout[n*4+2] = oy/nn; xout[n*4+3] = oz/nn;
}

__global__ void loss_kernel(const float* __restrict__ gt,
                            const float* __restrict__ x,
                            const int* __restrict__ row,
                            const int* __restrict__ col,
                            const float* __restrict__ beta_p,
                            float* __restrict__ loss_acc) {
    int e = blockIdx.x * blockDim.x + threadIdx.x;
    float local = 0.f;
    if (e < N_EDGES) {
        int r = row[e], c = col[e];
        float aw = gt[c*4+0], ax = gt[c*4+1], ay = gt[c*4+2], az = gt[c*4+3];
        float bw = gt[r*4+0], bx = -gt[r*4+1], by = -gt[r*4+2], bz = -gt[r*4+3];
        float gw,gx,gy,gz;
        qmul4(aw,ax,ay,az, bw,bx,by,bz, gw,gx,gy,gz);
        float cw2 = x[c*4+0], cx2 = x[c*4+1], cy2 = x[c*4+2], cz2 = x[c*4+3];
        float dw = x[r*4+0], dx = -x[r*4+1], dy = -x[r*4+2], dz = -x[r*4+3];
        float xw,xx,xy,xz;
        qmul4(cw2,cx2,cy2,cz2, dw,dx,dy,dz, xw,xx,xy,xz);
        float lw,lx,ly,lz;
        qmul4(gw,-gx,-gy,-gz, xw,xx,xy,xz, lw,lx,ly,lz);
        float nn = sqrtf(lw*lw + lx*lx + ly*ly + lz*lz);
        nn = fmaxf(nn, 1e-12f);
        lw /= nn; lx /= nn; ly /= nn; lz /= nn;
        float beta = beta_p[0];
        float d[4] = {fabsf(lw - 1.f), fabsf(lx), fabsf(ly), fabsf(lz)};
#pragma unroll
        for (int i = 0; i < 4; i++) {
            float v = d[i];
            local += (v < beta) ? (0.5f * v * v / beta) : (v - 0.5f * beta);
        }
    }
    __shared__ float sm[256];
    sm[threadIdx.x] = local;
    __syncthreads();
    for (int s = 128; s > 0; s >>= 1) {
        if (threadIdx.x < s) sm[threadIdx.x] += sm[threadIdx.x + s];
        __syncthreads();
    }
    if (threadIdx.x == 0) atomicAdd(loss_acc, sm[0]);
}

__global__ void finalize_kernel(const float* __restrict__ loss_acc,
                                const float* __restrict__ beta_p,
                                float* __restrict__ out) {
    out[OFF_LOSS] = loss_acc[0] / (float)(N_EDGES * 4);
    out[OFF_BETA] = beta_p[0];
}

__global__ void outres_kernel(const float* __restrict__ e4,
                              const float* __restrict__ w,
                              const float* __restrict__ b,
                              float* __restrict__ out) {
    int gw = (blockIdx.x * blockDim.x + threadIdx.x) >> 5;
    int lane = threadIdx.x & 31;
    if (gw >= N_EDGES) return;
    float s = 0.f;
#pragma unroll
    for (int k = lane; k < 128; k += 32)
        s = fmaf(e4[(size_t)gw * 128 + k], w[k], s);
#pragma unroll
    for (int o = 16; o > 0; o >>= 1) s += __shfl_down_sync(0xFFFFFFFFu, s, o);
    if (lane == 0) out[OFF_RES + gw] = s + b[0];
}

// ---------------- host ----------------
extern "C" void kernel_launch(void* const* d_in, const int* in_sizes, int n_in,
                              void* d_out, int out_size) {
    const float* x_org     = (const float*)d_in[0];
    const float* edge_attr = (const float*)d_in[1];
    const float* gt_q      = (const float*)d_in[2];
    const float* beta      = (const float*)d_in[3];
    const float* node_feat = (const float*)d_in[4];
    const float* edge_feat = (const float*)d_in[5];
    const float* W1 = (const float*)d_in[6];
    const float* b1 = (const float*)d_in[7];
    const float* W2 = (const float*)d_in[8];
    const float* b2 = (const float*)d_in[9];
    const float* W3 = (const float*)d_in[10];
    const float* b3 = (const float*)d_in[11];
    const float* W4 = (const float*)d_in[12];
    const float* b4 = (const float*)d_in[13];
    const float* lin1_w = (const float*)d_in[14];
    const float* lin1_b = (const float*)d_in[15];
    const float* lin2_w = (const float*)d_in[16];
    const float* lin2_b = (const float*)d_in[17];
    const int* ei = (const int*)d_in[18];
    const int* row = ei;
    const int* col = ei + N_EDGES;

    float* out = (float*)d_out;
    float* x1 = out + OFF_X1;
    float* x2 = out + OFF_X2;
    float* x3 = out + OFF_X3;
    float* x4 = out + OFF_X4;
    float* e1 = out + OFF_E1;
    float* e2 = out + OFF_E2;
    float* e3 = out + OFF_E3;
    float* e4 = out + OFF_E4;

    float *xsum, *lossacc, *nf_t, *xorg_t, *ef_t, *eam_t;
    float *x1t, *x2t, *x3t, *e1t, *e2t, *e3t, *Wt;
    int* cnt;
    cudaGetSymbolAddress((void**)&xsum, g_xsum);
    cudaGetSymbolAddress((void**)&lossacc, g_loss);
    cudaGetSymbolAddress((void**)&cnt, g_cnt);
    cudaGetSymbolAddress((void**)&nf_t, g_nf_t);
    cudaGetSymbolAddress((void**)&xorg_t, g_xorg_t);
    cudaGetSymbolAddress((void**)&ef_t, g_ef_t);
    cudaGetSymbolAddress((void**)&eam_t, g_eam_t);
    cudaGetSymbolAddress((void**)&x1t, g_x1t);
    cudaGetSymbolAddress((void**)&x2t, g_x2t);
    cudaGetSymbolAddress((void**)&x3t, g_x3t);
    cudaGetSymbolAddress((void**)&e1t, g_e1t);
    cudaGetSymbolAddress((void**)&e2t, g_e2t);
    cudaGetSymbolAddress((void**)&e3t, g_e3t);
    cudaGetSymbolAddress((void**)&Wt, g_Wt);

    float* W1t = Wt;
    float* W2t = Wt + 396 * 128;
    float* W3t = Wt + (396 + 388) * 128;
    float* W4t = Wt + (396 + 388 + 768) * 128;

    zero_i<<<(N_NODES + 255)/256, 256>>>(cnt, N_NODES);
    zero_f<<<1, 32>>>(lossacc, 1);
    prep_kernel<<<(N_EDGES + 255)/256, 256>>>(x_org, edge_attr, row, col, eam_t, cnt);

    conv_tf32<<<(N_NODES*128 + 255)/256, 256>>>(node_feat, nf_t, N_NODES*128);
    conv_tf32<<<(N_NODES*4 + 255)/256, 256>>>(x_org, xorg_t, N_NODES*4);
    conv_tf32<<<(N_EDGES*128 + 255)/256, 256>>>(edge_feat, ef_t, N_EDGES*128);
    conv_tf32<<<(396*128 + 255)/256, 256>>>(W1, W1t, 396*128);
    conv_tf32<<<(388*128 + 255)/256, 256>>>(W2, W2t, 388*128);
    conv_tf32<<<(768*128 + 255)/256, 256>>>(W3, W3t, 768*128);
    conv_tf32<<<(768*128 + 255)/256, 256>>>(W4, W4t, 768*128);

    const int GRID = (N_EDGES + BM - 1) / BM;
    auto run_layer = [&](GemmParams& p, float* xout, float* xt) {
        edge_gemm_tc<<<GRID, 256>>>(p);
        node_update<<<(N_NODES*128 + 255)/256, 256>>>(xsum, cnt, xout, xt, N_NODES*128);
    };

    // Layer 1
    {
        GemmParams p;
        p.base[0]=nf_t;   p.mode[0]=0; p.end[0]=128;
        p.base[1]=xorg_t; p.mode[1]=0; p.end[1]=132;
        p.base[2]=nf_t;   p.mode[2]=1; p.end[2]=260;
        p.base[3]=xorg_t; p.mode[3]=1; p.end[3]=264;
        p.base[4]=ef_t;   p.mode[4]=2; p.end[4]=392;
        p.base[5]=eam_t;  p.mode[5]=2; p.end[5]=396;
        p.nsegs=6; p.K=396; p.W=W1t; p.b=b1; p.e_out=e1; p.et=e1t;
        p.xsum=xsum; p.row=row; p.col=col;
        run_layer(p, x1, x1t);
    }
    // Layer 2
    {
        GemmParams p;
        p.base[0]=x1t;   p.mode[0]=0; p.end[0]=128;
        p.base[1]=x1t;   p.mode[1]=1; p.end[1]=256;
        p.base[2]=eam_t; p.mode[2]=2; p.end[2]=260;
        p.base[3]=e1t;   p.mode[3]=2; p.end[3]=388;
        p.nsegs=4; p.K=388; p.W=W2t; p.b=b2; p.e_out=e2; p.et=e2t;
        p.xsum=xsum; p.row=row; p.col=col;
        run_layer(p, x2, x2t);
    }
    // Layer 3
    {
        GemmParams p;
        p.base[0]=x2t; p.mode[0]=0; p.end[0]=128;
        p.base[1]=x1t; p.mode[1]=0; p.end[1]=256;
        p.base[2]=x2t; p.mode[2]=1; p.end[2]=384;
        p.base[3]=x1t; p.mode[3]=1; p.end[3]=512;
        p.base[4]=e2t; p.mode[4]=2; p.end[4]=640;
        p.base[5]=e1t; p.mode[5]=2; p.end[5]=768;
        p.nsegs=6; p.K=768; p.W=W3t; p.b=b3; p.e_out=e3; p.et=e3t;
        p.xsum=xsum; p.row=row; p.col=col;
        run_layer(p, x3, x3t);
    }
    // Layer 4
    {
        GemmParams p;
        p.base[0]=x3t; p.mode[0]=0; p.end[0]=128;
        p.base[1]=x2t; p.mode[1]=0; p.end[1]=256;
        p.base[2]=x3t; p.mode[2]=1; p.end[2]=384;
        p.base[3]=x2t; p.mode[3]=1; p.end[3]=512;
        p.base[4]=e3t; p.mode[4]=2; p.end[4]=640;
        p.base[5]=e2t; p.mode[5]=2; p.end[5]=768;
        p.nsegs=6; p.K=768; p.W=W4t; p.b=b4; p.e_out=e4; p.et=nullptr;
        p.xsum=xsum; p.row=row; p.col=col;
        run_layer(p, x4, nullptr);
    }

    lin1_kernel<<<(N_NODES + 255)/256, 256>>>(x4, lin1_w, lin1_b, x_org, out + OFF_X);
    loss_kernel<<<(N_EDGES + 255)/256, 256>>>(gt_q, out + OFF_X, row, col, beta, lossacc);
    finalize_kernel<<<1, 1>>>(lossacc, beta, out);
    outres_kernel<<<(N_EDGES*32 + 255)/256, 256>>>(e4, lin2_w, lin2_b, out);

    (void)in_sizes; (void)n_in; (void)out_size;
}

// round 5
// speedup vs baseline: 5.2499x; 1.1696x over previous
#include <cuda_runtime.h>
#include <math.h>

#define N_NODES 10000
#define N_EDGES 200000

// ---- output offsets (pytree leaf order) ----
#define OFF_X     0
#define OFF_LOSS  40000
#define OFF_BETA  40001
#define OFF_RES   40002
#define OFF_X1    240002
#define OFF_X2    1520002
#define OFF_X3    2800002
#define OFF_X4    4080002
#define OFF_E1    5360002
#define OFF_E2    30960002
#define OFF_E3    56560002
#define OFF_E4    82160002

// ---- scratch (no allocations allowed) ----
__device__ float g_xsum[N_NODES * 128];   // zero-init at load; invariant: zero after each launch
__device__ int   g_cnt[N_NODES];
__device__ float g_loss[1];
// tf32-rounded operand copies
__device__ float g_nf_t[N_NODES * 128];
__device__ float g_xorg_t[N_NODES * 4];
__device__ float g_ef_t[N_EDGES * 128];
__device__ float g_eam_t[N_EDGES * 4];
__device__ float g_x1t[N_NODES * 128];
__device__ float g_x2t[N_NODES * 128];
__device__ float g_x3t[N_NODES * 128];
__device__ float g_e1t[N_EDGES * 128];
__device__ float g_e2t[N_EDGES * 128];
__device__ float g_e3t[N_EDGES * 128];
// permuted tf32 weights: per chunk 2048 floats in MMA fragment order
// chunks: L1 25, L2 25, L3 48, L4 48  -> total 146*2048 = 299008
__device__ float g_PW[299008];

__device__ __forceinline__ unsigned f2tf32(float f) {
    unsigned u;
    asm("cvt.rna.tf32.f32 %0, %1;" : "=r"(u) : "f"(f));
    return u;
}
__device__ __forceinline__ float tf32f(float f) { return __uint_as_float(f2tf32(f)); }

__device__ __forceinline__ void qmul4(float qw,float qx,float qy,float qz,
                                      float rw,float rx,float ry,float rz,
                                      float& ow,float& ox,float& oy,float& oz) {
    ow = qw*rw - qx*rx - qy*ry - qz*rz;
    ox = qw*rx + qx*rw + qy*rz - qz*ry;
    oy = qw*ry - qx*rz + qy*rw + qz*rx;
    oz = qw*rz + qx*ry - qy*rx + qz*rw;
}

// ---------------- small kernels ----------------
__global__ void zero_f(float* p, int n) {
    int i = blockIdx.x * blockDim.x + threadIdx.x;
    if (i < n) p[i] = 0.f;
}
__global__ void zero_i(int* p, int n) {
    int i = blockIdx.x * blockDim.x + threadIdx.x;
    if (i < n) p[i] = 0;
}
__global__ void conv_tf32(const float* __restrict__ in, float* __restrict__ out, int n) {
    int i = blockIdx.x * blockDim.x + threadIdx.x;
    if (i < n) out[i] = tf32f(in[i]);
}

// permute W (K x 128, row-major) into fragment order + tf32 round.
// out chunk layout (2048 floats): idx = (((wn*2+ks)*4+q)*32+lane)*4+elem
//   k = ch*16 + ks*8 + tg + (elem&1)*4 ; n = wn*64 + (2q+(elem>>1))*8 + g
__global__ void permW_kernel(const float* __restrict__ W, float* __restrict__ PW,
                             int K, int nCh) {
    int o = blockIdx.x * blockDim.x + threadIdx.x;
    if (o >= nCh * 2048) return;
    int ch = o >> 11, r = o & 2047;
    int wn = r >> 10, r2 = r & 1023;
    int ks = r2 >> 9, r3 = r2 & 511;
    int q  = r3 >> 7, r4 = r3 & 127;
    int lane = r4 >> 2, elem = r4 & 3;
    int g = lane >> 2, tg = lane & 3;
    int j = 2*q + (elem >> 1);
    int k = ch*16 + ks*8 + tg + (elem & 1)*4;
    int n = wn*64 + j*8 + g;
    PW[o] = (k < K) ? tf32f(W[(size_t)k * 128 + n]) : 0.f;
}

// eam = qmul(qmul(inv(x_org[col]), edge_attr), x_org[row]) -> tf32; count rows
__global__ void prep_kernel(const float* __restrict__ x_org,
                            const float* __restrict__ edge_attr,
                            const int* __restrict__ row,
                            const int* __restrict__ col,
                            float* __restrict__ eam_t,
                            int* __restrict__ cnt) {
    int e = blockIdx.x * blockDim.x + threadIdx.x;
    if (e >= N_EDGES) return;
    int r = row[e], c = col[e];
    float cw = x_org[c*4+0], cx = -x_org[c*4+1], cy = -x_org[c*4+2], cz = -x_org[c*4+3];
    float aw = edge_attr[e*4+0], ax = edge_attr[e*4+1], ay = edge_attr[e*4+2], az = edge_attr[e*4+3];
    float tw,tx,ty,tz;
    qmul4(cw,cx,cy,cz, aw,ax,ay,az, tw,tx,ty,tz);
    float rw = x_org[r*4+0], rx = x_org[r*4+1], ry = x_org[r*4+2], rz = x_org[r*4+3];
    float ow,ox,oy,oz;
    qmul4(tw,tx,ty,tz, rw,rx,ry,rz, ow,ox,oy,oz);
    eam_t[e*4+0]=tf32f(ow); eam_t[e*4+1]=tf32f(ox);
    eam_t[e*4+2]=tf32f(oy); eam_t[e*4+3]=tf32f(oz);
    atomicAdd(&cnt[r], 1);
}

// ---------------- fused gather + tf32 tensor GEMM ----------------
struct GemmParams {
    const float* base[6];
    int end[6];
    int mode[6];           // 0=row, 1=col, 2=edge
    int nsegs;
    int K;
    const float* PW;       // permuted tf32 weights
    const float* b;
    float* e_out;
    float* et;             // tf32 echo or nullptr
    float* xsum;
    const int* row;
    const int* col;
};

#define BM 128
#define BK 16
#define A_ST 20    // bank (20m+k)%32 bijective over fragment lanes

__device__ __forceinline__ void cpa16(unsigned dst, const float* src, int sz) {
    asm volatile("cp.async.cg.shared.global [%0], [%1], 16, %2;"
                 :: "r"(dst), "l"(src), "r"(sz));
}
__device__ __forceinline__ void cp_commit() {
    asm volatile("cp.async.commit_group;");
}
template<int N> __device__ __forceinline__ void cp_wait() {
    asm volatile("cp.async.wait_group %0;" :: "n"(N));
}

__global__ void __launch_bounds__(256, 2)
edge_gemm_tc(GemmParams p) {
    __shared__ __align__(16) float As[2][BM * A_ST];
    __shared__ __align__(16) float Bs[2][2048];

    int tid = threadIdx.x;
    int lane = tid & 31, wrp = tid >> 5;
    int e_base = blockIdx.x * BM;

    // gather role: one thread = one edge (me), half the k-range (kpair)
    int me = tid >> 1, kpair = tid & 1;
    int ge = min(e_base + me, N_EDGES - 1);
    int er = p.row[ge], ec = p.col[ge];

    // compute role: warp (wm,wn) does 32x64 at (wm*32, wn*64)
    int wm = wrp & 3, wn = wrp >> 2;
    int m0 = wm * 32, nb = wn * 64;
    int g = lane >> 2, tg = lane & 3;

    float acc[2][8][4];
#pragma unroll
    for (int mt = 0; mt < 2; mt++)
#pragma unroll
        for (int j = 0; j < 8; j++)
#pragma unroll
            for (int c = 0; c < 4; c++) acc[mt][j][c] = 0.f;

    int nCh = (p.K + BK - 1) / BK;

    auto load_tile = [&](int ch, int buf) {
        int k0 = ch * BK;
        // A: 2 x cpa16 (4 contiguous k's each) per thread
#pragma unroll
        for (int u = 0; u < 2; u++) {
            int koff = kpair * 8 + u * 4;
            int k = k0 + koff;
            const float* src = p.base[0];
            int sz = 0;
            int start = 0;
#pragma unroll
            for (int s = 0; s < 6; s++) {
                if (s < p.nsegs && k < p.end[s]) {
                    int width = p.end[s] - start;
                    int idx = (p.mode[s] == 0) ? er : ((p.mode[s] == 1) ? ec : ge);
                    src = p.base[s] + (size_t)idx * width + (k - start);
                    sz = 16;
                    break;
                }
                start = p.end[s];
            }
            unsigned dst = (unsigned)__cvta_generic_to_shared(&As[buf][me * A_ST + koff]);
            cpa16(dst, src, sz);
        }
        // B: linear copy of permuted chunk (2048 floats)
        const float* pw = p.PW + (size_t)ch * 2048;
#pragma unroll
        for (int u = 0; u < 2; u++) {
            int i4 = tid + u * 256;
            unsigned dst = (unsigned)__cvta_generic_to_shared(&Bs[buf][i4 * 4]);
            cpa16(dst, pw + i4 * 4, 16);
        }
    };

    auto compute = [&](int buf) {
#pragma unroll
        for (int ks = 0; ks < 2; ks++) {
            int kk = ks * 8;
            unsigned a[2][4];
#pragma unroll
            for (int mt = 0; mt < 2; mt++) {
                int r = m0 + mt * 16;
                a[mt][0] = __float_as_uint(As[buf][(r + g    ) * A_ST + kk + tg    ]);
                a[mt][1] = __float_as_uint(As[buf][(r + g + 8) * A_ST + kk + tg    ]);
                a[mt][2] = __float_as_uint(As[buf][(r + g    ) * A_ST + kk + tg + 4]);
                a[mt][3] = __float_as_uint(As[buf][(r + g + 8) * A_ST + kk + tg + 4]);
            }
#pragma unroll
            for (int q = 0; q < 4; q++) {
                float4 bv = *reinterpret_cast<const float4*>(
                    &Bs[buf][(((wn*2 + ks)*4 + q)*32 + lane)*4]);
                unsigned b00 = __float_as_uint(bv.x), b01 = __float_as_uint(bv.y);
                unsigned b10 = __float_as_uint(bv.z), b11 = __float_as_uint(bv.w);
                int j0 = 2*q, j1 = 2*q + 1;
#pragma unroll
                for (int mt = 0; mt < 2; mt++) {
                    asm volatile(
                        "mma.sync.aligned.m16n8k8.row.col.f32.tf32.tf32.f32 "
                        "{%0,%1,%2,%3}, {%4,%5,%6,%7}, {%8,%9}, {%0,%1,%2,%3};"
                        : "+f"(acc[mt][j0][0]), "+f"(acc[mt][j0][1]),
                          "+f"(acc[mt][j0][2]), "+f"(acc[mt][j0][3])
                        : "r"(a[mt][0]), "r"(a[mt][1]), "r"(a[mt][2]), "r"(a[mt][3]),
                          "r"(b00), "r"(b01));
                    asm volatile(
                        "mma.sync.aligned.m16n8k8.row.col.f32.tf32.tf32.f32 "
                        "{%0,%1,%2,%3}, {%4,%5,%6,%7}, {%8,%9}, {%0,%1,%2,%3};"
                        : "+f"(acc[mt][j1][0]), "+f"(acc[mt][j1][1]),
                          "+f"(acc[mt][j1][2]), "+f"(acc[mt][j1][3])
                        : "r"(a[mt][0]), "r"(a[mt][1]), "r"(a[mt][2]), "r"(a[mt][3]),
                          "r"(b10), "r"(b11));
                }
            }
        }
    };

    // 2-stage pipeline
    load_tile(0, 0); cp_commit();
    if (nCh > 1) { load_tile(1, 1); cp_commit(); }
    for (int ch = 0; ch < nCh; ch++) {
        if (ch + 1 < nCh) cp_wait<1>(); else cp_wait<0>();
        __syncthreads();
        compute(ch & 1);
        __syncthreads();
        if (ch + 2 < nCh) { load_tile(ch + 2, ch & 1); cp_commit(); }
    }

    // ---- epilogue ----
#pragma unroll
    for (int mt = 0; mt < 2; mt++) {
        int eA = e_base + m0 + mt * 16 + g;
        int eB = eA + 8;
        bool vA = eA < N_EDGES, vB = eB < N_EDGES;
        int rA = vA ? p.row[eA] : 0;
        int rB = vB ? p.row[eB] : 0;
#pragma unroll
        for (int j = 0; j < 8; j++) {
            int n = nb + j*8 + tg*2;
            float b0 = p.b[n], b1 = p.b[n+1];
            float mA0 = acc[mt][j][0] + b0, mA1 = acc[mt][j][1] + b1;
            float mB0 = acc[mt][j][2] + b0, mB1 = acc[mt][j][3] + b1;
            if (vA) {
                float oa0 = fmaxf(mA0, 0.f), oa1 = fmaxf(mA1, 0.f);
                *reinterpret_cast<float2*>(&p.e_out[(size_t)eA*128 + n]) = make_float2(oa0, oa1);
                if (p.et)
                    *reinterpret_cast<float2*>(&p.et[(size_t)eA*128 + n]) =
                        make_float2(tf32f(oa0), tf32f(oa1));
                atomicAdd(&p.xsum[rA*128 + n    ], mA0);
                atomicAdd(&p.xsum[rA*128 + n + 1], mA1);
            }
            if (vB) {
                float ob0 = fmaxf(mB0, 0.f), ob1 = fmaxf(mB1, 0.f);
                *reinterpret_cast<float2*>(&p.e_out[(size_t)eB*128 + n]) = make_float2(ob0, ob1);
                if (p.et)
                    *reinterpret_cast<float2*>(&p.et[(size_t)eB*128 + n]) =
                        make_float2(tf32f(ob0), tf32f(ob1));
                atomicAdd(&p.xsum[rB*128 + n    ], mB0);
                atomicAdd(&p.xsum[rB*128 + n + 1], mB1);
            }
        }
    }
}

// x_next = relu(xsum / max(cnt,1)); resets xsum; optional tf32 copy
__global__ void node_update(float* __restrict__ xsum,
                            const int* __restrict__ cnt,
                            float* __restrict__ xout,
                            float* __restrict__ xt, int n_elems) {
    int i = blockIdx.x * blockDim.x + threadIdx.x;
    if (i >= n_elems) return;
    int node = i >> 7;
    float c = (float)max(cnt[node], 1);
    float v = xsum[i];
    xsum[i] = 0.f;
    float x = fmaxf(v / c, 0.f);
    xout[i] = x;
    if (xt) xt[i] = tf32f(x);
}

__global__ void lin1_kernel(const float* __restrict__ x4,
                            const float* __restrict__ w,
                            const float* __restrict__ bb,
                            const float* __restrict__ x_org,
                            float* __restrict__ xout) {
    int n = blockIdx.x * blockDim.x + threadIdx.x;
    if (n >= N_NODES) return;
    float q0 = bb[0], q1 = bb[1], q2 = bb[2], q3 = bb[3];
    for (int k = 0; k < 128; k++) {
        float v = x4[(size_t)n * 128 + k];
        q0 = fmaf(v, w[k*4+0], q0);
        q1 = fmaf(v, w[k*4+1], q1);
        q2 = fmaf(v, w[k*4+2], q2);
        q3 = fmaf(v, w[k*4+3], q3);
    }
    float rw = x_org[n*4+0], rx = x_org[n*4+1], ry = x_org[n*4+2], rz = x_org[n*4+3];
    float ow,ox,oy,oz;
    qmul4(q0,q1,q2,q3, rw,rx,ry,rz, ow,ox,oy,oz);
    float nn = sqrtf(ow*ow + ox*ox + oy*oy + oz*oz);
    nn = fmaxf(nn, 1e-12f);
    xout[n*4+0] = ow/nn; xout[n*4+1] = ox/nn; xout[n*4+2] = oy/nn; xout[n*4+3] = oz/nn;
}

__global__ void loss_kernel(const float* __restrict__ gt,
                            const float* __restrict__ x,
                            const int* __restrict__ row,
                            const int* __restrict__ col,
                            const float* __restrict__ beta_p,
                            float* __restrict__ loss_acc) {
    int e = blockIdx.x * blockDim.x + threadIdx.x;
    float local = 0.f;
    if (e < N_EDGES) {
        int r = row[e], c = col[e];
        float aw = gt[c*4+0], ax = gt[c*4+1], ay = gt[c*4+2], az = gt[c*4+3];
        float bw = gt[r*4+0], bx = -gt[r*4+1], by = -gt[r*4+2], bz = -gt[r*4+3];
        float gw,gx,gy,gz;
        qmul4(aw,ax,ay,az, bw,bx,by,bz, gw,gx,gy,gz);
        float cw2 = x[c*4+0], cx2 = x[c*4+1], cy2 = x[c*4+2], cz2 = x[c*4+3];
        float dw = x[r*4+0], dx = -x[r*4+1], dy = -x[r*4+2], dz = -x[r*4+3];
        float xw,xx,xy,xz;
        qmul4(cw2,cx2,cy2,cz2, dw,dx,dy,dz, xw,xx,xy,xz);
        float lw,lx,ly,lz;
        qmul4(gw,-gx,-gy,-gz, xw,xx,xy,xz, lw,lx,ly,lz);
        float nn = sqrtf(lw*lw + lx*lx + ly*ly + lz*lz);
        nn = fmaxf(nn, 1e-12f);
        lw /= nn; lx /= nn; ly /= nn; lz /= nn;
        float beta = beta_p[0];
        float d[4] = {fabsf(lw - 1.f), fabsf(lx), fabsf(ly), fabsf(lz)};
#pragma unroll
        for (int i = 0; i < 4; i++) {
            float v = d[i];
            local += (v < beta) ? (0.5f * v * v / beta) : (v - 0.5f * beta);
        }
    }
    __shared__ float sm[256];
    sm[threadIdx.x] = local;
    __syncthreads();
    for (int s = 128; s > 0; s >>= 1) {
        if (threadIdx.x < s) sm[threadIdx.x] += sm[threadIdx.x + s];
        __syncthreads();
    }
    if (threadIdx.x == 0) atomicAdd(loss_acc, sm[0]);
}

__global__ void finalize_kernel(const float* __restrict__ loss_acc,
                                const float* __restrict__ beta_p,
                                float* __restrict__ out) {
    out[OFF_LOSS] = loss_acc[0] / (float)(N_EDGES * 4);
    out[OFF_BETA] = beta_p[0];
}

__global__ void outres_kernel(const float* __restrict__ e4,
                              const float* __restrict__ w,
                              const float* __restrict__ b,
                              float* __restrict__ out) {
    int gw = (blockIdx.x * blockDim.x + threadIdx.x) >> 5;
    int lane = threadIdx.x & 31;
    if (gw >= N_EDGES) return;
    float s = 0.f;
#pragma unroll
    for (int k = lane; k < 128; k += 32)
        s = fmaf(e4[(size_t)gw * 128 + k], w[k], s);
#pragma unroll
    for (int o = 16; o > 0; o >>= 1) s += __shfl_down_sync(0xFFFFFFFFu, s, o);
    if (lane == 0) out[OFF_RES + gw] = s + b[0];
}

// ---------------- host ----------------
extern "C" void kernel_launch(void* const* d_in, const int* in_sizes, int n_in,
                              void* d_out, int out_size) {
    const float* x_org     = (const float*)d_in[0];
    const float* edge_attr = (const float*)d_in[1];
    const float* gt_q      = (const float*)d_in[2];
    const float* beta      = (const float*)d_in[3];
    const float* node_feat = (const float*)d_in[4];
    const float* edge_feat = (const float*)d_in[5];
    const float* W1 = (const float*)d_in[6];
    const float* b1 = (const float*)d_in[7];
    const float* W2 = (const float*)d_in[8];
    const float* b2 = (const float*)d_in[9];
    const float* W3 = (const float*)d_in[10];
    const float* b3 = (const float*)d_in[11];
    const float* W4 = (const float*)d_in[12];
    const float* b4 = (const float*)d_in[13];
    const float* lin1_w = (const float*)d_in[14];
    const float* lin1_b = (const float*)d_in[15];
    const float* lin2_w = (const float*)d_in[16];
    const float* lin2_b = (const float*)d_in[17];
    const int* ei = (const int*)d_in[18];
    const int* row = ei;
    const int* col = ei + N_EDGES;

    float* out = (float*)d_out;
    float* x1 = out + OFF_X1;
    float* x2 = out + OFF_X2;
    float* x3 = out + OFF_X3;
    float* x4 = out + OFF_X4;
    float* e1 = out + OFF_E1;
    float* e2 = out + OFF_E2;
    float* e3 = out + OFF_E3;
    float* e4 = out + OFF_E4;

    float *xsum, *lossacc, *nf_t, *xorg_t, *ef_t, *eam_t;
    float *x1t, *x2t, *x3t, *e1t, *e2t, *e3t, *PW;
    int* cnt;
    cudaGetSymbolAddress((void**)&xsum, g_xsum);
    cudaGetSymbolAddress((void**)&lossacc, g_loss);
    cudaGetSymbolAddress((void**)&cnt, g_cnt);
    cudaGetSymbolAddress((void**)&nf_t, g_nf_t);
    cudaGetSymbolAddress((void**)&xorg_t, g_xorg_t);
    cudaGetSymbolAddress((void**)&ef_t, g_ef_t);
    cudaGetSymbolAddress((void**)&eam_t, g_eam_t);
    cudaGetSymbolAddress((void**)&x1t, g_x1t);
    cudaGetSymbolAddress((void**)&x2t, g_x2t);
    cudaGetSymbolAddress((void**)&x3t, g_x3t);
    cudaGetSymbolAddress((void**)&e1t, g_e1t);
    cudaGetSymbolAddress((void**)&e2t, g_e2t);
    cudaGetSymbolAddress((void**)&e3t, g_e3t);
    cudaGetSymbolAddress((void**)&PW, g_PW);

    // chunk counts + permuted offsets
    const int nCh1 = 25, nCh2 = 25, nCh3 = 48, nCh4 = 48;
    float* PW1 = PW;
    float* PW2 = PW + nCh1 * 2048;
    float* PW3 = PW + (nCh1 + nCh2) * 2048;
    float* PW4 = PW + (nCh1 + nCh2 + nCh3) * 2048;

    zero_i<<<(N_NODES + 255)/256, 256>>>(cnt, N_NODES);
    zero_f<<<1, 32>>>(lossacc, 1);
    prep_kernel<<<(N_EDGES + 255)/256, 256>>>(x_org, edge_attr, row, col, eam_t, cnt);

    conv_tf32<<<(N_NODES*128 + 255)/256, 256>>>(node_feat, nf_t, N_NODES*128);
    conv_tf32<<<(N_NODES*4 + 255)/256, 256>>>(x_org, xorg_t, N_NODES*4);
    conv_tf32<<<(N_EDGES*128 + 255)/256, 256>>>(edge_feat, ef_t, N_EDGES*128);
    permW_kernel<<<(nCh1*2048 + 255)/256, 256>>>(W1, PW1, 396, nCh1);
    permW_kernel<<<(nCh2*2048 + 255)/256, 256>>>(W2, PW2, 388, nCh2);
    permW_kernel<<<(nCh3*2048 + 255)/256, 256>>>(W3, PW3, 768, nCh3);
    permW_kernel<<<(nCh4*2048 + 255)/256, 256>>>(W4, PW4, 768, nCh4);

    const int GRID = (N_EDGES + BM - 1) / BM;
    auto run_layer = [&](GemmParams& p, float* xout, float* xt) {
        edge_gemm_tc<<<GRID, 256>>>(p);
        node_update<<<(N_NODES*128 + 255)/256, 256>>>(xsum, cnt, xout, xt, N_NODES*128);
    };

    // Layer 1
    {
        GemmParams p;
        p.base[0]=nf_t;   p.mode[0]=0; p.end[0]=128;
        p.base[1]=xorg_t; p.mode[1]=0; p.end[1]=132;
        p.base[2]=nf_t;   p.mode[2]=1; p.end[2]=260;
        p.base[3]=xorg_t; p.mode[3]=1; p.end[3]=264;
        p.base[4]=ef_t;   p.mode[4]=2; p.end[4]=392;
        p.base[5]=eam_t;  p.mode[5]=2; p.end[5]=396;
        p.nsegs=6; p.K=396; p.PW=PW1; p.b=b1; p.e_out=e1; p.et=e1t;
        p.xsum=xsum; p.row=row; p.col=col;
        run_layer(p, x1, x1t);
    }
    // Layer 2
    {
        GemmParams p;
        p.base[0]=x1t;   p.mode[0]=0; p.end[0]=128;
        p.base[1]=x1t;   p.mode[1]=1; p.end[1]=256;
        p.base[2]=eam_t; p.mode[2]=2; p.end[2]=260;
        p.base[3]=e1t;   p.mode[3]=2; p.end[3]=388;
        p.nsegs=4; p.K=388; p.PW=PW2; p.b=b2; p.e_out=e2; p.et=e2t;
        p.xsum=xsum; p.row=row; p.col=col;
        run_layer(p, x2, x2t);
    }
    // Layer 3
    {
        GemmParams p;
        p.base[0]=x2t; p.mode[0]=0; p.end[0]=128;
        p.base[1]=x1t; p.mode[1]=0; p.end[1]=256;
        p.base[2]=x2t; p.mode[2]=1; p.end[2]=384;
        p.base[3]=x1t; p.mode[3]=1; p.end[3]=512;
        p.base[4]=e2t; p.mode[4]=2; p.end[4]=640;
        p.base[5]=e1t; p.mode[5]=2; p.end[5]=768;
        p.nsegs=6; p.K=768; p.PW=PW3; p.b=b3; p.e_out=e3; p.et=e3t;
        p.xsum=xsum; p.row=row; p.col=col;
        run_layer(p, x3, x3t);
    }
    // Layer 4
    {
        GemmParams p;
        p.base[0]=x3t; p.mode[0]=0; p.end[0]=128;
        p.base[1]=x2t; p.mode[1]=0; p.end[1]=256;
        p.base[2]=x3t; p.mode[2]=1; p.end[2]=384;
        p.base[3]=x2t; p.mode[3]=1; p.end[3]=512;
        p.base[4]=e3t; p.mode[4]=2; p.end[4]=640;
        p.base[5]=e2t; p.mode[5]=2; p.end[5]=768;
        p.nsegs=6; p.K=768; p.PW=PW4; p.b=b4; p.e_out=e4; p.et=nullptr;
        p.xsum=xsum; p.row=row; p.col=col;
        run_layer(p, x4, nullptr);
    }

    lin1_kernel<<<(N_NODES + 255)/256, 256>>>(x4, lin1_w, lin1_b, x_org, out + OFF_X);
    loss_kernel<<<(N_EDGES + 255)/256, 256>>>(gt_q, out + OFF_X, row, col, beta, lossacc);
    finalize_kernel<<<1, 1>>>(lossacc, beta, out);
    outres_kernel<<<(N_EDGES*32 + 255)/256, 256>>>(e4, lin2_w, lin2_b, out);

    (void)in_sizes; (void)n_in; (void)out_size;
}

// round 6
// speedup vs baseline: 5.2676x; 1.0034x over previous
#include <cuda_runtime.h>
#include <math.h>

#define N_NODES 10000
#define N_EDGES 200000

// ---- output offsets (pytree leaf order) ----
#define OFF_X     0
#define OFF_LOSS  40000
#define OFF_BETA  40001
#define OFF_RES   40002
#define OFF_X1    240002
#define OFF_X2    1520002
#define OFF_X3    2800002
#define OFF_X4    4080002
#define OFF_E1    5360002
#define OFF_E2    30960002
#define OFF_E3    56560002
#define OFF_E4    82160002

// ---- scratch ----
__device__ float g_xsum[N_NODES * 128];   // zero-init at load; invariant: zero after each launch
__device__ int   g_cnt[N_NODES];
__device__ float g_loss[1];
__device__ float g_nf_t[N_NODES * 128];
__device__ float g_ef_t[N_EDGES * 128];
__device__ float g_side[N_EDGES * 32];    // [eam(4) | xorg_row(4) | xorg_col(4) | zeros(20)] tf32
__device__ float g_x1t[N_NODES * 128];
__device__ float g_x2t[N_NODES * 128];
__device__ float g_x3t[N_NODES * 128];
__device__ float g_e1t[N_EDGES * 128];
__device__ float g_e2t[N_EDGES * 128];
__device__ float g_e3t[N_EDGES * 128];
// permuted tf32 weights, 4096 floats per BK=32 chunk; chunks 13+13+24+24 = 74
__device__ float g_PW[74 * 4096];

__device__ __forceinline__ unsigned f2tf32(float f) {
    unsigned u;
    asm("cvt.rna.tf32.f32 %0, %1;" : "=r"(u) : "f"(f));
    return u;
}
__device__ __forceinline__ float tf32f(float f) { return __uint_as_float(f2tf32(f)); }

__device__ __forceinline__ void qmul4(float qw,float qx,float qy,float qz,
                                      float rw,float rx,float ry,float rz,
                                      float& ow,float& ox,float& oy,float& oz) {
    ow = qw*rw - qx*rx - qy*ry - qz*rz;
    ox = qw*rx + qx*rw + qy*rz - qz*ry;
    oy = qw*ry - qx*rz + qy*rw + qz*rx;
    oz = qw*rz + qx*ry - qy*rx + qz*rw;
}

// ---------------- small kernels ----------------
__global__ void zero_f(float* p, int n) {
    int i = blockIdx.x * blockDim.x + threadIdx.x;
    if (i < n) p[i] = 0.f;
}
__global__ void zero_i(int* p, int n) {
    int i = blockIdx.x * blockDim.x + threadIdx.x;
    if (i < n) p[i] = 0;
}
__global__ void conv_tf32(const float* __restrict__ in, float* __restrict__ out, int n) {
    int i = blockIdx.x * blockDim.x + threadIdx.x;
    if (i < n) out[i] = tf32f(in[i]);
}

// permute W rows (source K x 128) into BK=32-chunk MMA fragment order with K-remap.
// chunk layout (4096 floats): idx = (((wn*4+ks)*4+q)*32+lane)*4+elem
//   kprime = ch*32 + ks*8 + tg + (elem&1)*4 ; n = wn*64 + (2q+(elem>>1))*8 + g
struct PermParams { int dst[6]; int src[6]; int len[6]; int nseg; int nCh; };
__global__ void permW_kernel(const float* __restrict__ W, float* __restrict__ PW,
                             PermParams pp) {
    int o = blockIdx.x * blockDim.x + threadIdx.x;
    if (o >= pp.nCh * 4096) return;
    int ch = o >> 12, r = o & 4095;
    int wn = r >> 11, r2 = r & 2047;
    int ks = r2 >> 9, r3 = r2 & 511;
    int q  = r3 >> 7, r4 = r3 & 127;
    int lane = r4 >> 2, elem = r4 & 3;
    int g = lane >> 2, tg = lane & 3;
    int kp = ch*32 + ks*8 + tg + (elem & 1)*4;
    int n  = wn*64 + (2*q + (elem >> 1))*8 + g;
    float v = 0.f;
#pragma unroll
    for (int s = 0; s < 6; s++) {
        if (s < pp.nseg && kp >= pp.dst[s] && kp < pp.dst[s] + pp.len[s]) {
            v = tf32f(W[(size_t)(pp.src[s] + kp - pp.dst[s]) * 128 + n]);
            break;
        }
    }
    PW[o] = v;
}

// side table + row counts
__global__ void prep_kernel(const float* __restrict__ x_org,
                            const float* __restrict__ edge_attr,
                            const int* __restrict__ row,
                            const int* __restrict__ col,
                            float* __restrict__ side,
                            int* __restrict__ cnt) {
    int e = blockIdx.x * blockDim.x + threadIdx.x;
    if (e >= N_EDGES) return;
    int r = row[e], c = col[e];
    float cw = x_org[c*4+0], cx = -x_org[c*4+1], cy = -x_org[c*4+2], cz = -x_org[c*4+3];
    float aw = edge_attr[e*4+0], ax = edge_attr[e*4+1], ay = edge_attr[e*4+2], az = edge_attr[e*4+3];
    float tw,tx,ty,tz;
    qmul4(cw,cx,cy,cz, aw,ax,ay,az, tw,tx,ty,tz);
    float rw = x_org[r*4+0], rx = x_org[r*4+1], ry = x_org[r*4+2], rz = x_org[r*4+3];
    float ow,ox,oy,oz;
    qmul4(tw,tx,ty,tz, rw,rx,ry,rz, ow,ox,oy,oz);
    float* s = side + (size_t)e * 32;
    s[0]=tf32f(ow); s[1]=tf32f(ox); s[2]=tf32f(oy); s[3]=tf32f(oz);
    s[4]=tf32f(rw); s[5]=tf32f(rx); s[6]=tf32f(ry); s[7]=tf32f(rz);
    s[8]=tf32f(x_org[c*4+0]); s[9]=tf32f(x_org[c*4+1]);
    s[10]=tf32f(x_org[c*4+2]); s[11]=tf32f(x_org[c*4+3]);
#pragma unroll
    for (int i = 12; i < 32; i++) s[i] = 0.f;
    atomicAdd(&cnt[r], 1);
}

// ---------------- bulk-TMA gather + tf32 tensor GEMM ----------------
struct ChunkDesc { const float* base; int widthF; int offF; int mode; };
struct GemmParams {
    ChunkDesc cd[24];
    int nCh;
    const float* PW;
    const float* b;
    float* e_out;
    float* et;            // tf32 echo or nullptr
    float* xsum;
    const int* row;
    const int* col;
};

#define BM 128
#define A_ST 36           // 144B rows: bulk-dst 16B-aligned, bank (4m+k)%32 bijective
#define A_SZ (BM * A_ST)  // 4608 floats
#define B_SZ 4096
#define SMEM_FLOATS (2*A_SZ + 2*B_SZ)
#define SMEM_BYTES  (SMEM_FLOATS*4 + 16)

__device__ __forceinline__ void bulk_g2s(unsigned dst, const float* src, unsigned bytes,
                                         unsigned mbar) {
    asm volatile(
        "cp.async.bulk.shared::cluster.global.mbarrier::complete_tx::bytes [%0], [%1], %2, [%3];"
        :: "r"(dst), "l"(src), "r"(bytes), "r"(mbar) : "memory");
}
__device__ __forceinline__ void mbar_init(unsigned mbar, unsigned cnt) {
    asm volatile("mbarrier.init.shared.b64 [%0], %1;" :: "r"(mbar), "r"(cnt) : "memory");
}
__device__ __forceinline__ void mbar_expect(unsigned mbar, unsigned bytes) {
    asm volatile("mbarrier.arrive.expect_tx.shared.b64 _, [%0], %1;"
                 :: "r"(mbar), "r"(bytes) : "memory");
}
__device__ __forceinline__ void mbar_wait(unsigned mbar, unsigned parity) {
    asm volatile(
        "{\n\t.reg .pred P;\n\t"
        "WAIT_%=:\n\t"
        "mbarrier.try_wait.parity.acquire.cta.shared::cta.b64 P, [%0], %1, 0x989680;\n\t"
        "@P bra.uni DONE_%=;\n\t"
        "bra.uni WAIT_%=;\n\t"
        "DONE_%=:\n\t}"
        :: "r"(mbar), "r"(parity) : "memory");
}

__global__ void __launch_bounds__(256, 2)
edge_gemm_tc(const __grid_constant__ GemmParams p) {
    extern __shared__ __align__(16) float smem[];
    float* AsP[2] = { smem, smem + A_SZ };
    float* BsP[2] = { smem + 2*A_SZ, smem + 2*A_SZ + B_SZ };
    unsigned mbar0 = (unsigned)__cvta_generic_to_shared(smem + SMEM_FLOATS);
    unsigned mb[2] = { mbar0, mbar0 + 8 };
    unsigned AsU[2] = { (unsigned)__cvta_generic_to_shared(AsP[0]),
                        (unsigned)__cvta_generic_to_shared(AsP[1]) };
    unsigned BsU[2] = { (unsigned)__cvta_generic_to_shared(BsP[0]),
                        (unsigned)__cvta_generic_to_shared(BsP[1]) };

    int tid = threadIdx.x;
    int lane = tid & 31, wrp = tid >> 5;
    int e_base = blockIdx.x * BM;

    if (tid == 0) { mbar_init(mb[0], 1); mbar_init(mb[1], 1); }
    __syncthreads();

    // gather role: thread t (<128) owns edge e_base+t
    int ge = 0, er = 0, ec = 0;
    if (tid < 128) {
        ge = min(e_base + tid, N_EDGES - 1);
        er = p.row[ge];
        ec = p.col[ge];
    }

    // compute role: warp (wm,wn) does 32x64 at (wm*32, wn*64)
    int wm = wrp & 3, wn = wrp >> 2;
    int m0 = wm * 32, nb = wn * 64;
    int g = lane >> 2, tg = lane & 3;

    float acc[2][8][4];
#pragma unroll
    for (int mt = 0; mt < 2; mt++)
#pragma unroll
        for (int j = 0; j < 8; j++)
#pragma unroll
            for (int c = 0; c < 4; c++) acc[mt][j][c] = 0.f;

    int nCh = p.nCh;

    auto issue = [&](int ch, int buf) {
        if (tid < 128) {
            ChunkDesc d = p.cd[ch];
            int idx = (d.mode == 0) ? er : ((d.mode == 1) ? ec : ge);
            const float* src = d.base + (size_t)idx * d.widthF + d.offF;
            bulk_g2s(AsU[buf] + tid * (A_ST * 4), src, 128, mb[buf]);
            if (tid == 0) {
                bulk_g2s(BsU[buf], p.PW + (size_t)ch * 4096, 16384, mb[buf]);
                mbar_expect(mb[buf], 128 * 128 + 16384);
            }
        }
    };

    auto compute = [&](int buf) {
        const float* As = AsP[buf];
        const float* Bs = BsP[buf];
#pragma unroll
        for (int ks = 0; ks < 4; ks++) {
            int kk = ks * 8;
            unsigned a[2][4];
#pragma unroll
            for (int mt = 0; mt < 2; mt++) {
                int r = m0 + mt * 16;
                a[mt][0] = __float_as_uint(As[(r + g    ) * A_ST + kk + tg    ]);
                a[mt][1] = __float_as_uint(As[(r + g + 8) * A_ST + kk + tg    ]);
                a[mt][2] = __float_as_uint(As[(r + g    ) * A_ST + kk + tg + 4]);
                a[mt][3] = __float_as_uint(As[(r + g + 8) * A_ST + kk + tg + 4]);
            }
#pragma unroll
            for (int q = 0; q < 4; q++) {
                float4 bv = *reinterpret_cast<const float4*>(
                    &Bs[(((wn*4 + ks)*4 + q)*32 + lane)*4]);
                unsigned b00 = __float_as_uint(bv.x), b01 = __float_as_uint(bv.y);
                unsigned b10 = __float_as_uint(bv.z), b11 = __float_as_uint(bv.w);
                int j0 = 2*q, j1 = 2*q + 1;
#pragma unroll
                for (int mt = 0; mt < 2; mt++) {
                    asm volatile(
                        "mma.sync.aligned.m16n8k8.row.col.f32.tf32.tf32.f32 "
                        "{%0,%1,%2,%3}, {%4,%5,%6,%7}, {%8,%9}, {%0,%1,%2,%3};"
                        : "+f"(acc[mt][j0][0]), "+f"(acc[mt][j0][1]),
                          "+f"(acc[mt][j0][2]), "+f"(acc[mt][j0][3])
                        : "r"(a[mt][0]), "r"(a[mt][1]), "r"(a[mt][2]), "r"(a[mt][3]),
                          "r"(b00), "r"(b01));
                    asm volatile(
                        "mma.sync.aligned.m16n8k8.row.col.f32.tf32.tf32.f32 "
                        "{%0,%1,%2,%3}, {%4,%5,%6,%7}, {%8,%9}, {%0,%1,%2,%3};"
                        : "+f"(acc[mt][j1][0]), "+f"(acc[mt][j1][1]),
                          "+f"(acc[mt][j1][2]), "+f"(acc[mt][j1][3])
                        : "r"(a[mt][0]), "r"(a[mt][1]), "r"(a[mt][2]), "r"(a[mt][3]),
                          "r"(b10), "r"(b11));
                }
            }
        }
    };

    issue(0, 0);
    issue(1, 1);
    for (int ch = 0; ch < nCh; ch++) {
        int buf = ch & 1;
        mbar_wait(mb[buf], (ch >> 1) & 1);
        compute(buf);
        __syncthreads();
        if (ch + 2 < nCh) issue(ch + 2, buf);
    }

    // ---- epilogue ----
#pragma unroll
    for (int mt = 0; mt < 2; mt++) {
        int eA = e_base + m0 + mt * 16 + g;
        int eB = eA + 8;
        bool vA = eA < N_EDGES, vB = eB < N_EDGES;
        int rA = vA ? p.row[eA] : 0;
        int rB = vB ? p.row[eB] : 0;
#pragma unroll
        for (int j = 0; j < 8; j++) {
            int n = nb + j*8 + tg*2;
            float b0 = p.b[n], b1 = p.b[n+1];
            float mA0 = acc[mt][j][0] + b0, mA1 = acc[mt][j][1] + b1;
            float mB0 = acc[mt][j][2] + b0, mB1 = acc[mt][j][3] + b1;
            if (vA) {
                float oa0 = fmaxf(mA0, 0.f), oa1 = fmaxf(mA1, 0.f);
                *reinterpret_cast<float2*>(&p.e_out[(size_t)eA*128 + n]) = make_float2(oa0, oa1);
                if (p.et)
                    *reinterpret_cast<float2*>(&p.et[(size_t)eA*128 + n]) =
                        make_float2(tf32f(oa0), tf32f(oa1));
                atomicAdd(&p.xsum[rA*128 + n    ], mA0);
                atomicAdd(&p.xsum[rA*128 + n + 1], mA1);
            }
            if (vB) {
                float ob0 = fmaxf(mB0, 0.f), ob1 = fmaxf(mB1, 0.f);
                *reinterpret_cast<float2*>(&p.e_out[(size_t)eB*128 + n]) = make_float2(ob0, ob1);
                if (p.et)
                    *reinterpret_cast<float2*>(&p.et[(size_t)eB*128 + n]) =
                        make_float2(tf32f(ob0), tf32f(ob1));
                atomicAdd(&p.xsum[rB*128 + n    ], mB0);
                atomicAdd(&p.xsum[rB*128 + n + 1], mB1);
            }
        }
    }
}

// x_next = relu(xsum / max(cnt,1)); resets xsum; optional tf32 copy
__global__ void node_update(float* __restrict__ xsum,
                            const int* __restrict__ cnt,
                            float* __restrict__ xout,
                            float* __restrict__ xt, int n_elems) {
    int i = blockIdx.x * blockDim.x + threadIdx.x;
    if (i >= n_elems) return;
    int node = i >> 7;
    float c = (float)max(cnt[node], 1);
    float v = xsum[i];
    xsum[i] = 0.f;
    float x = fmaxf(v / c, 0.f);
    xout[i] = x;
    if (xt) xt[i] = tf32f(x);
}

__global__ void lin1_kernel(const float* __restrict__ x4,
                            const float* __restrict__ w,
                            const float* __restrict__ bb,
                            const float* __restrict__ x_org,
                            float* __restrict__ xout) {
    int n = blockIdx.x * blockDim.x + threadIdx.x;
    if (n >= N_NODES) return;
    float q0 = bb[0], q1 = bb[1], q2 = bb[2], q3 = bb[3];
    for (int k = 0; k < 128; k++) {
        float v = x4[(size_t)n * 128 + k];
        q0 = fmaf(v, w[k*4+0], q0);
        q1 = fmaf(v, w[k*4+1], q1);
        q2 = fmaf(v, w[k*4+2], q2);
        q3 = fmaf(v, w[k*4+3], q3);
    }
    float rw = x_org[n*4+0], rx = x_org[n*4+1], ry = x_org[n*4+2], rz = x_org[n*4+3];
    float ow,ox,oy,oz;
    qmul4(q0,q1,q2,q3, rw,rx,ry,rz, ow,ox,oy,oz);
    float nn = sqrtf(ow*ow + ox*ox + oy*oy + oz*oz);
    nn = fmaxf(nn, 1e-12f);
    xout[n*4+0] = ow/nn; xout[n*4+1] = ox/nn; xout[n*4+2] = oy/nn; xout[n*4+3] = oz/nn;
}

__global__ void loss_kernel(const float* __restrict__ gt,
                            const float* __restrict__ x,
                            const int* __restrict__ row,
                            const int* __restrict__ col,
                            const float* __restrict__ beta_p,
                            float* __restrict__ loss_acc) {
    int e = blockIdx.x * blockDim.x + threadIdx.x;
    float local = 0.f;
    if (e < N_EDGES) {
        int r = row[e], c = col[e];
        float aw = gt[c*4+0], ax = gt[c*4+1], ay = gt[c*4+2], az = gt[c*4+3];
        float bw = gt[r*4+0], bx = -gt[r*4+1], by = -gt[r*4+2], bz = -gt[r*4+3];
        float gw,gx,gy,gz;
        qmul4(aw,ax,ay,az, bw,bx,by,bz, gw,gx,gy,gz);
        float cw2 = x[c*4+0], cx2 = x[c*4+1], cy2 = x[c*4+2], cz2 = x[c*4+3];
        float dw = x[r*4+0], dx = -x[r*4+1], dy = -x[r*4+2], dz = -x[r*4+3];
        float xw,xx,xy,xz;
        qmul4(cw2,cx2,cy2,cz2, dw,dx,dy,dz, xw,xx,xy,xz);
        float lw,lx,ly,lz;
        qmul4(gw,-gx,-gy,-gz, xw,xx,xy,xz, lw,lx,ly,lz);
        float nn = sqrtf(lw*lw + lx*lx + ly*ly + lz*lz);
        nn = fmaxf(nn, 1e-12f);
        lw /= nn; lx /= nn; ly /= nn; lz /= nn;
        float beta = beta_p[0];
        float d[4] = {fabsf(lw - 1.f), fabsf(lx), fabsf(ly), fabsf(lz)};
#pragma unroll
        for (int i = 0; i < 4; i++) {
            float v = d[i];
            local += (v < beta) ? (0.5f * v * v / beta) : (v - 0.5f * beta);
        }
    }
    __shared__ float sm[256];
    sm[threadIdx.x] = local;
    __syncthreads();
    for (int s = 128; s > 0; s >>= 1) {
        if (threadIdx.x < s) sm[threadIdx.x] += sm[threadIdx.x + s];
        __syncthreads();
    }
    if (threadIdx.x == 0) atomicAdd(loss_acc, sm[0]);
}

__global__ void finalize_kernel(const float* __restrict__ loss_acc,
                                const float* __restrict__ beta_p,
                                float* __restrict__ out) {
    out[OFF_LOSS] = loss_acc[0] / (float)(N_EDGES * 4);
    out[OFF_BETA] = beta_p[0];
}

__global__ void outres_kernel(const float* __restrict__ e4,
                              const float* __restrict__ w,
                              const float* __restrict__ b,
                              float* __restrict__ out) {
    int gw = (blockIdx.x * blockDim.x + threadIdx.x) >> 5;
    int lane = threadIdx.x & 31;
    if (gw >= N_EDGES) return;
    float s = 0.f;
#pragma unroll
    for (int k = lane; k < 128; k += 32)
        s = fmaf(e4[(size_t)gw * 128 + k], w[k], s);
#pragma unroll
    for (int o = 16; o > 0; o >>= 1) s += __shfl_down_sync(0xFFFFFFFFu, s, o);
    if (lane == 0) out[OFF_RES + gw] = s + b[0];
}

// ---------------- host ----------------
extern "C" void kernel_launch(void* const* d_in, const int* in_sizes, int n_in,
                              void* d_out, int out_size) {
    const float* x_org     = (const float*)d_in[0];
    const float* edge_attr = (const float*)d_in[1];
    const float* gt_q      = (const float*)d_in[2];
    const float* beta      = (const float*)d_in[3];
    const float* node_feat = (const float*)d_in[4];
    const float* edge_feat = (const float*)d_in[5];
    const float* W1 = (const float*)d_in[6];
    const float* b1 = (const float*)d_in[7];
    const float* W2 = (const float*)d_in[8];
    const float* b2 = (const float*)d_in[9];
    const float* W3 = (const float*)d_in[10];
    const float* b3 = (const float*)d_in[11];
    const float* W4 = (const float*)d_in[12];
    const float* b4 = (const float*)d_in[13];
    const float* lin1_w = (const float*)d_in[14];
    const float* lin1_b = (const float*)d_in[15];
    const float* lin2_w = (const float*)d_in[16];
    const float* lin2_b = (const float*)d_in[17];
    const int* ei = (const int*)d_in[18];
    const int* row = ei;
    const int* col = ei + N_EDGES;

    float* out = (float*)d_out;
    float* x1 = out + OFF_X1;
    float* x2 = out + OFF_X2;
    float* x3 = out + OFF_X3;
    float* x4 = out + OFF_X4;
    float* e1 = out + OFF_E1;
    float* e2 = out + OFF_E2;
    float* e3 = out + OFF_E3;
    float* e4 = out + OFF_E4;

    float *xsum, *lossacc, *nf_t, *ef_t, *side;
    float *x1t, *x2t, *x3t, *e1t, *e2t, *e3t, *PW;
    int* cnt;
    cudaGetSymbolAddress((void**)&xsum, g_xsum);
    cudaGetSymbolAddress((void**)&lossacc, g_loss);
    cudaGetSymbolAddress((void**)&cnt, g_cnt);
    cudaGetSymbolAddress((void**)&nf_t, g_nf_t);
    cudaGetSymbolAddress((void**)&ef_t, g_ef_t);
    cudaGetSymbolAddress((void**)&side, g_side);
    cudaGetSymbolAddress((void**)&x1t, g_x1t);
    cudaGetSymbolAddress((void**)&x2t, g_x2t);
    cudaGetSymbolAddress((void**)&x3t, g_x3t);
    cudaGetSymbolAddress((void**)&e1t, g_e1t);
    cudaGetSymbolAddress((void**)&e2t, g_e2t);
    cudaGetSymbolAddress((void**)&e3t, g_e3t);
    cudaGetSymbolAddress((void**)&PW, g_PW);

    const int nCh1 = 13, nCh2 = 13, nCh3 = 24, nCh4 = 24;
    float* PW1 = PW;
    float* PW2 = PW + nCh1 * 4096;
    float* PW3 = PW + (nCh1 + nCh2) * 4096;
    float* PW4 = PW + (nCh1 + nCh2 + nCh3) * 4096;

    cudaFuncSetAttribute(edge_gemm_tc, cudaFuncAttributeMaxDynamicSharedMemorySize, SMEM_BYTES);

    zero_i<<<(N_NODES + 255)/256, 256>>>(cnt, N_NODES);
    zero_f<<<1, 32>>>(lossacc, 1);
    prep_kernel<<<(N_EDGES + 255)/256, 256>>>(x_org, edge_attr, row, col, side, cnt);

    conv_tf32<<<(N_NODES*128 + 255)/256, 256>>>(node_feat, nf_t, N_NODES*128);
    conv_tf32<<<(N_EDGES*128 + 255)/256, 256>>>(edge_feat, ef_t, N_EDGES*128);

    // permW maps: dst (our K order) <- src (original W rows)
    {   // L1: W rows [nf_r 0-127 | xorg_r 128-131 | nf_c 132-259 | xorg_c 260-263 | ef 264-391 | eam 392-395]
        PermParams pp;
        pp.dst[0]=0;   pp.src[0]=0;   pp.len[0]=128;  // nf[row]
        pp.dst[1]=128; pp.src[1]=132; pp.len[1]=128;  // nf[col]
        pp.dst[2]=256; pp.src[2]=264; pp.len[2]=128;  // ef
        pp.dst[3]=384; pp.src[3]=392; pp.len[3]=4;    // side: eam
        pp.dst[4]=388; pp.src[4]=128; pp.len[4]=4;    // side: xorg[row]
        pp.dst[5]=392; pp.src[5]=260; pp.len[5]=4;    // side: xorg[col]
        pp.nseg=6; pp.nCh=nCh1;
        permW_kernel<<<(nCh1*4096 + 255)/256, 256>>>(W1, PW1, pp);
    }
    {   // L2: W rows [x1r 0-127 | x1c 128-255 | eam 256-259 | e1 260-387]
        PermParams pp;
        pp.dst[0]=0;   pp.src[0]=0;   pp.len[0]=128;
        pp.dst[1]=128; pp.src[1]=128; pp.len[1]=128;
        pp.dst[2]=256; pp.src[2]=260; pp.len[2]=128;  // e1
        pp.dst[3]=384; pp.src[3]=256; pp.len[3]=4;    // side: eam
        pp.dst[4]=0; pp.src[4]=0; pp.len[4]=0;
        pp.dst[5]=0; pp.src[5]=0; pp.len[5]=0;
        pp.nseg=4; pp.nCh=nCh2;
        permW_kernel<<<(nCh2*4096 + 255)/256, 256>>>(W2, PW2, pp);
    }
    {   // L3/L4 identity
        PermParams pp;
        pp.dst[0]=0; pp.src[0]=0; pp.len[0]=768;
        for (int s = 1; s < 6; s++) { pp.dst[s]=0; pp.src[s]=0; pp.len[s]=0; }
        pp.nseg=1; pp.nCh=nCh3;
        permW_kernel<<<(nCh3*4096 + 255)/256, 256>>>(W3, PW3, pp);
        permW_kernel<<<(nCh4*4096 + 255)/256, 256>>>(W4, PW4, pp);
    }

    const int GRID = (N_EDGES + BM - 1) / BM;
    auto run_layer = [&](GemmParams& p, float* xout, float* xt) {
        edge_gemm_tc<<<GRID, 256, SMEM_BYTES>>>(p);
        node_update<<<(N_NODES*128 + 255)/256, 256>>>(xsum, cnt, xout, xt, N_NODES*128);
    };
    auto seg4 = [&](GemmParams& p, int c0, const float* base, int mode) {
        for (int i = 0; i < 4; i++) {
            p.cd[c0+i].base = base; p.cd[c0+i].widthF = 128;
            p.cd[c0+i].offF = i*32; p.cd[c0+i].mode = mode;
        }
    };

    // Layer 1: chunks [nf_r x4 | nf_c x4 | ef x4 | side]
    {
        GemmParams p;
        seg4(p, 0, nf_t, 0);
        seg4(p, 4, nf_t, 1);
        seg4(p, 8, ef_t, 2);
        p.cd[12].base = side; p.cd[12].widthF = 32; p.cd[12].offF = 0; p.cd[12].mode = 2;
        p.nCh = nCh1; p.PW = PW1; p.b = b1; p.e_out = e1; p.et = e1t;
        p.xsum = xsum; p.row = row; p.col = col;
        run_layer(p, x1, x1t);
    }
    // Layer 2: [x1_r x4 | x1_c x4 | e1 x4 | side]
    {
        GemmParams p;
        seg4(p, 0, x1t, 0);
        seg4(p, 4, x1t, 1);
        seg4(p, 8, e1t, 2);
        p.cd[12].base = side; p.cd[12].widthF = 32; p.cd[12].offF = 0; p.cd[12].mode = 2;
        p.nCh = nCh2; p.PW = PW2; p.b = b2; p.e_out = e2; p.et = e2t;
        p.xsum = xsum; p.row = row; p.col = col;
        run_layer(p, x2, x2t);
    }
    // Layer 3: [x2_r | x1_r | x2_c | x1_c | e2 | e1] x4 each
    {
        GemmParams p;
        seg4(p, 0,  x2t, 0);
        seg4(p, 4,  x1t, 0);
        seg4(p, 8,  x2t, 1);
        seg4(p, 12, x1t, 1);
        seg4(p, 16, e2t, 2);
        seg4(p, 20, e1t, 2);
        p.nCh = nCh3; p.PW = PW3; p.b = b3; p.e_out = e3; p.et = e3t;
        p.xsum = xsum; p.row = row; p.col = col;
        run_layer(p, x3, x3t);
    }
    // Layer 4: [x3_r | x2_r | x3_c | x2_c | e3 | e2]
    {
        GemmParams p;
        seg4(p, 0,  x3t, 0);
        seg4(p, 4,  x2t, 0);
        seg4(p, 8,  x3t, 1);
        seg4(p, 12, x2t, 1);
        seg4(p, 16, e3t, 2);
        seg4(p, 20, e2t, 2);
        p.nCh = nCh4; p.PW = PW4; p.b = b4; p.e_out = e4; p.et = nullptr;
        p.xsum = xsum; p.row = row; p.col = col;
        run_layer(p, x4, nullptr);
    }

    lin1_kernel<<<(N_NODES + 255)/256, 256>>>(x4, lin1_w, lin1_b, x_org, out + OFF_X);
    loss_kernel<<<(N_EDGES + 255)/256, 256>>>(gt_q, out + OFF_X, row, col, beta, lossacc);
    finalize_kernel<<<1, 1>>>(lossacc, beta, out);
    outres_kernel<<<(N_EDGES*32 + 255)/256, 256>>>(e4, lin2_w, lin2_b, out);

    (void)in_sizes; (void)n_in; (void)out_size;
}